// round 1
// baseline (speedup 1.0000x reference)
#include <cuda_runtime.h>
#include <math.h>

// Problem constants
#define BSZ 2
#define LSEQ 2048
#define DMODEL 2048
#define NHEAD 32
#define HDIM 64
#define MROWS (BSZ * LSEQ)     // 4096
#define NQKV (3 * DMODEL)      // 6144

// Scratch (device globals; no allocation allowed in kernel_launch)
__device__ float g_qkv[(size_t)MROWS * NQKV];   // [B*L, 3*D]  ~100MB
__device__ float g_q[(size_t)MROWS * DMODEL];   // [B,H,L,hd]
__device__ float g_k[(size_t)MROWS * DMODEL];   // [B,H,L,hd]
__device__ float g_v[(size_t)MROWS * DMODEL];   // [B,H,L,hd]
__device__ float g_ao[(size_t)MROWS * DMODEL];  // [B*L, H*hd] attention out

// ---------------------------------------------------------------------------
// Tiled SGEMM (NT): C[M,N] = A[M,K] @ B[N,K]^T.  BM=BN=64, BK=16, 256 thr,
// each thread computes a 4x4 micro-tile. M,N multiples of 64; K multiple of 16.
// ---------------------------------------------------------------------------
__device__ __forceinline__ void sgemm_nt_body(const float* __restrict__ A,
                                              const float* __restrict__ B,
                                              float* __restrict__ C,
                                              int N, int K) {
    __shared__ float As[16][64];
    __shared__ float Bs[16][64];

    const int tid  = threadIdx.x;          // 0..255
    const int row0 = blockIdx.y * 64;
    const int col0 = blockIdx.x * 64;

    const int lr = tid >> 2;               // 0..63 : tile row for loading
    const int lc = (tid & 3) * 4;          // 0,4,8,12 : k-offset for loading
    const int ty = tid >> 4;               // 0..15 : output row group
    const int tx = tid & 15;               // 0..15 : output col group

    float acc[4][4];
#pragma unroll
    for (int i = 0; i < 4; i++)
#pragma unroll
        for (int j = 0; j < 4; j++) acc[i][j] = 0.f;

    const float* Ap = A + (size_t)(row0 + lr) * K + lc;
    const float* Bp = B + (size_t)(col0 + lr) * K + lc;

    for (int k0 = 0; k0 < K; k0 += 16) {
        float4 a = *(const float4*)(Ap + k0);
        float4 b = *(const float4*)(Bp + k0);
        As[lc + 0][lr] = a.x; As[lc + 1][lr] = a.y;
        As[lc + 2][lr] = a.z; As[lc + 3][lr] = a.w;
        Bs[lc + 0][lr] = b.x; Bs[lc + 1][lr] = b.y;
        Bs[lc + 2][lr] = b.z; Bs[lc + 3][lr] = b.w;
        __syncthreads();

#pragma unroll
        for (int kk = 0; kk < 16; kk++) {
            float4 av = *(const float4*)&As[kk][ty * 4];
            float4 bv = *(const float4*)&Bs[kk][tx * 4];
            float ar[4] = {av.x, av.y, av.z, av.w};
            float br[4] = {bv.x, bv.y, bv.z, bv.w};
#pragma unroll
            for (int i = 0; i < 4; i++)
#pragma unroll
                for (int j = 0; j < 4; j++)
                    acc[i][j] += ar[i] * br[j];
        }
        __syncthreads();
    }

#pragma unroll
    for (int i = 0; i < 4; i++) {
        float4 r = make_float4(acc[i][0], acc[i][1], acc[i][2], acc[i][3]);
        *(float4*)&C[(size_t)(row0 + ty * 4 + i) * N + col0 + tx * 4] = r;
    }
}

__global__ void __launch_bounds__(256)
k_gemm_qkv(const float* __restrict__ x, const float* __restrict__ wqkv) {
    sgemm_nt_body(x, wqkv, g_qkv, NQKV, DMODEL);
}

__global__ void __launch_bounds__(256)
k_gemm_out(const float* __restrict__ wo, float* __restrict__ out) {
    sgemm_nt_body(g_ao, wo, out, DMODEL, DMODEL);
}

// ---------------------------------------------------------------------------
// RoPE + split: reads g_qkv [B*L, 3, H, hd], writes g_q/g_k (rotated) and g_v
// in [B, H, L, hd] layout.  One thread per (b,l,h,d<32) pair.
// ---------------------------------------------------------------------------
__global__ void __launch_bounds__(256)
k_rope_split() {
    int idx = blockIdx.x * blockDim.x + threadIdx.x;  // < MROWS*NHEAD*32
    const int d  = idx & 31;
    const int h  = (idx >> 5) & 31;
    const int ml = idx >> 10;                         // 0..4095 = b*L + l
    if (ml >= MROWS) return;
    const int l  = ml & (LSEQ - 1);
    const int b  = ml >> 11;

    const size_t base = (size_t)ml * NQKV + (size_t)h * HDIM;
    float q1 = g_qkv[base + d];
    float q2 = g_qkv[base + d + 32];
    float k1 = g_qkv[base + DMODEL + d];
    float k2 = g_qkv[base + DMODEL + d + 32];
    float v1 = g_qkv[base + 2 * DMODEL + d];
    float v2 = g_qkv[base + 2 * DMODEL + d + 32];

    // inv_freq = 512^(-d/32) = 2^(-9d/32)
    float inv_freq = exp2f(-9.0f * (float)d / 32.0f);
    float f = (float)l * inv_freq;
    float s, c;
    sincosf(f, &s, &c);

    const size_t obase = (((size_t)b * NHEAD + h) * LSEQ + l) * HDIM;
    g_q[obase + d]      = q1 * c - q2 * s;
    g_q[obase + d + 32] = q2 * c + q1 * s;
    g_k[obase + d]      = k1 * c - k2 * s;
    g_k[obase + d + 32] = k2 * c + k1 * s;
    g_v[obase + d]      = v1;
    g_v[obase + d + 32] = v2;
}

// ---------------------------------------------------------------------------
// Flash attention (causal, online softmax).
// Grid: (L/64, B*H). Block: 64 threads, each owns one q row (q, o in regs).
// K/V tiles of 64x64 staged in shared memory (padded rows to dodge conflicts).
// Writes g_ao in [B*L, H*hd] layout for the epilogue GEMM.
// ---------------------------------------------------------------------------
__global__ void __launch_bounds__(64)
k_flash_attn() {
    __shared__ float Ks[64][68];
    __shared__ float Vs[64][68];

    const int tid = threadIdx.x;       // 0..63
    const int qt  = blockIdx.x;        // q tile
    const int bh  = blockIdx.y;        // b*NHEAD + h
    const int qr  = qt * 64 + tid;     // q row within sequence
    const float scale = 0.125f;        // 1/sqrt(64)

    const float* qptr = g_q + ((size_t)bh * LSEQ + qr) * HDIM;
    float4 q[16];
#pragma unroll
    for (int i = 0; i < 16; i++) q[i] = *(const float4*)(qptr + i * 4);

    float m = -1e30f, l = 0.f;
    float4 o[16];
#pragma unroll
    for (int i = 0; i < 16; i++) o[i] = make_float4(0.f, 0.f, 0.f, 0.f);

    for (int kt = 0; kt <= qt; ++kt) {
        const float* kptr = g_k + ((size_t)bh * LSEQ + kt * 64 + tid) * HDIM;
        const float* vptr = g_v + ((size_t)bh * LSEQ + kt * 64 + tid) * HDIM;
#pragma unroll
        for (int i = 0; i < 16; i++) {
            *(float4*)&Ks[tid][i * 4] = *(const float4*)(kptr + i * 4);
            *(float4*)&Vs[tid][i * 4] = *(const float4*)(vptr + i * 4);
        }
        __syncthreads();

        float s[64];
        float mt = m;
#pragma unroll
        for (int j = 0; j < 64; j++) {
            float acc = 0.f;
#pragma unroll
            for (int i = 0; i < 16; i++) {
                float4 kk = *(const float4*)&Ks[j][i * 4];
                acc += q[i].x * kk.x + q[i].y * kk.y + q[i].z * kk.z + q[i].w * kk.w;
            }
            acc *= scale;
            if (kt == qt && j > tid) acc = -1e30f;  // causal mask on diagonal tile
            s[j] = acc;
            mt = fmaxf(mt, acc);
        }

        float corr = __expf(m - mt);
        m = mt;
        l *= corr;
#pragma unroll
        for (int i = 0; i < 16; i++) {
            o[i].x *= corr; o[i].y *= corr; o[i].z *= corr; o[i].w *= corr;
        }

#pragma unroll
        for (int j = 0; j < 64; j++) {
            float p = __expf(s[j] - m);
            l += p;
#pragma unroll
            for (int i = 0; i < 16; i++) {
                float4 vv = *(const float4*)&Vs[j][i * 4];
                o[i].x += p * vv.x; o[i].y += p * vv.y;
                o[i].z += p * vv.z; o[i].w += p * vv.w;
            }
        }
        __syncthreads();
    }

    const float inv = 1.f / l;
    const int b = bh >> 5, h = bh & 31;
    float* optr = g_ao + ((size_t)(b * LSEQ + qr)) * DMODEL + (size_t)h * HDIM;
#pragma unroll
    for (int i = 0; i < 16; i++) {
        float4 r = make_float4(o[i].x * inv, o[i].y * inv, o[i].z * inv, o[i].w * inv);
        *(float4*)(optr + i * 4) = r;
    }
}

// ---------------------------------------------------------------------------
extern "C" void kernel_launch(void* const* d_in, const int* in_sizes, int n_in,
                              void* d_out, int out_size) {
    const float* x    = (const float*)d_in[0];
    const float* wqkv = (const float*)d_in[1];
    const float* wo   = (const float*)d_in[2];
    float* out        = (float*)d_out;

    // 1) QKV projection: g_qkv[4096,6144] = x[4096,2048] @ wqkv^T
    {
        dim3 grid(NQKV / 64, MROWS / 64);
        k_gemm_qkv<<<grid, 256>>>(x, wqkv);
    }
    // 2) RoPE + split into [B,H,L,hd]
    {
        int total = MROWS * NHEAD * 32;
        k_rope_split<<<(total + 255) / 256, 256>>>();
    }
    // 3) Causal flash attention -> g_ao [B*L, 2048]
    {
        dim3 grid(LSEQ / 64, BSZ * NHEAD);
        k_flash_attn<<<grid, 64>>>();
    }
    // 4) Output projection: out = g_ao @ wo^T
    {
        dim3 grid(DMODEL / 64, MROWS / 64);
        k_gemm_out<<<grid, 256>>>(wo, out);
    }
}

// round 2
// speedup vs baseline: 1.6400x; 1.6400x over previous
#include <cuda_runtime.h>
#include <math.h>
#include <stdint.h>

// Problem constants
#define BSZ 2
#define LSEQ 2048
#define DMODEL 2048
#define NHEAD 32
#define HDIM 64
#define MROWS (BSZ * LSEQ)     // 4096
#define NQKV (3 * DMODEL)      // 6144

// Scratch (device globals; no allocation allowed in kernel_launch)
__device__ float g_qkv[(size_t)MROWS * NQKV];   // [B*L, 3*D]
__device__ float g_q[(size_t)MROWS * DMODEL];   // [B,H,L,hd]
__device__ float g_k[(size_t)MROWS * DMODEL];   // [B,H,L,hd]
__device__ float g_v[(size_t)MROWS * DMODEL];   // [B,H,L,hd]
__device__ float g_ao[(size_t)MROWS * DMODEL];  // [B*L, H*hd]

__device__ __forceinline__ uint32_t f2tf32(float x) {
    uint32_t y;
    asm("cvt.rna.tf32.f32 %0, %1;" : "=r"(y) : "f"(x));
    return y;
}

// ---------------------------------------------------------------------------
// TF32 tensor-core GEMM (NT): C[M,N] = A[M,K] @ B[N,K]^T
// Block tile 128x128, BK=16, 256 threads (8 warps, 2x4), warp tile 64x32.
// mma.sync.aligned.m16n8k8.row.col.f32.tf32.tf32.f32
// M,N multiples of 128; K multiple of 16.
// ---------------------------------------------------------------------------
__global__ void __launch_bounds__(256)
k_gemm_tf32(const float* __restrict__ A, const float* __restrict__ B,
            float* __restrict__ C, int N, int K) {
    // [row][k] layout, stride 20 -> conflict-free fragment loads
    __shared__ uint32_t As[128][20];
    __shared__ uint32_t Bs[128][20];

    const int tid  = threadIdx.x;
    const int row0 = blockIdx.y * 128;
    const int col0 = blockIdx.x * 128;
    const int warp = tid >> 5, lane = tid & 31;
    const int wr = warp & 1;        // 0..1  -> 64-row slab
    const int wc = warp >> 1;       // 0..3  -> 32-col slab
    const int g  = lane >> 2;       // 0..7
    const int c  = lane & 3;        // 0..3

    float acc[4][4][4];
#pragma unroll
    for (int mt = 0; mt < 4; mt++)
#pragma unroll
        for (int nt = 0; nt < 4; nt++)
#pragma unroll
            for (int i = 0; i < 4; i++) acc[mt][nt][i] = 0.f;

    for (int k0 = 0; k0 < K; k0 += 16) {
        // Stage 128x16 tiles of A and B (converted to tf32-rna)
#pragma unroll
        for (int i = 0; i < 2; i++) {
            int u  = tid + i * 256;       // 0..511
            int r  = u >> 2;              // 0..127
            int kc = (u & 3) << 2;        // 0,4,8,12
            float4 a = *(const float4*)(A + (size_t)(row0 + r) * K + k0 + kc);
            float4 b = *(const float4*)(B + (size_t)(col0 + r) * K + k0 + kc);
            uint4 ua = make_uint4(f2tf32(a.x), f2tf32(a.y), f2tf32(a.z), f2tf32(a.w));
            uint4 ub = make_uint4(f2tf32(b.x), f2tf32(b.y), f2tf32(b.z), f2tf32(b.w));
            *(uint4*)&As[r][kc] = ua;
            *(uint4*)&Bs[r][kc] = ub;
        }
        __syncthreads();

#pragma unroll
        for (int ks = 0; ks < 16; ks += 8) {
            uint32_t af[4][4], bf[4][2];
#pragma unroll
            for (int mt = 0; mt < 4; mt++) {
                int rb = wr * 64 + mt * 16;
                af[mt][0] = As[rb + g][ks + c];
                af[mt][1] = As[rb + g + 8][ks + c];
                af[mt][2] = As[rb + g][ks + c + 4];
                af[mt][3] = As[rb + g + 8][ks + c + 4];
            }
#pragma unroll
            for (int nt = 0; nt < 4; nt++) {
                int cb = wc * 32 + nt * 8;
                bf[nt][0] = Bs[cb + g][ks + c];
                bf[nt][1] = Bs[cb + g][ks + c + 4];
            }
#pragma unroll
            for (int mt = 0; mt < 4; mt++)
#pragma unroll
                for (int nt = 0; nt < 4; nt++) {
                    asm volatile(
                        "mma.sync.aligned.m16n8k8.row.col.f32.tf32.tf32.f32 "
                        "{%0,%1,%2,%3}, {%4,%5,%6,%7}, {%8,%9}, {%0,%1,%2,%3};"
                        : "+f"(acc[mt][nt][0]), "+f"(acc[mt][nt][1]),
                          "+f"(acc[mt][nt][2]), "+f"(acc[mt][nt][3])
                        : "r"(af[mt][0]), "r"(af[mt][1]),
                          "r"(af[mt][2]), "r"(af[mt][3]),
                          "r"(bf[nt][0]), "r"(bf[nt][1]));
                }
        }
        __syncthreads();
    }

    // Epilogue: C fragment c0:(g,2c) c1:(g,2c+1) c2:(g+8,2c) c3:(g+8,2c+1)
#pragma unroll
    for (int mt = 0; mt < 4; mt++) {
        int r0 = row0 + wr * 64 + mt * 16 + g;
#pragma unroll
        for (int nt = 0; nt < 4; nt++) {
            int cc = col0 + wc * 32 + nt * 8 + c * 2;
            *(float2*)&C[(size_t)r0 * N + cc] =
                make_float2(acc[mt][nt][0], acc[mt][nt][1]);
            *(float2*)&C[(size_t)(r0 + 8) * N + cc] =
                make_float2(acc[mt][nt][2], acc[mt][nt][3]);
        }
    }
}

// ---------------------------------------------------------------------------
// RoPE + split: reads g_qkv [B*L, 3, H, hd], writes g_q/g_k (rotated) and g_v
// in [B, H, L, hd] layout.  One thread per (b,l,h,d<32) pair.
// ---------------------------------------------------------------------------
__global__ void __launch_bounds__(256)
k_rope_split() {
    int idx = blockIdx.x * blockDim.x + threadIdx.x;
    const int d  = idx & 31;
    const int h  = (idx >> 5) & 31;
    const int ml = idx >> 10;
    if (ml >= MROWS) return;
    const int l  = ml & (LSEQ - 1);
    const int b  = ml >> 11;

    const size_t base = (size_t)ml * NQKV + (size_t)h * HDIM;
    float q1 = g_qkv[base + d];
    float q2 = g_qkv[base + d + 32];
    float k1 = g_qkv[base + DMODEL + d];
    float k2 = g_qkv[base + DMODEL + d + 32];
    float v1 = g_qkv[base + 2 * DMODEL + d];
    float v2 = g_qkv[base + 2 * DMODEL + d + 32];

    float inv_freq = exp2f(-9.0f * (float)d / 32.0f);   // 512^(-d/32)
    float f = (float)l * inv_freq;
    float s, cc;
    sincosf(f, &s, &cc);

    const size_t obase = (((size_t)b * NHEAD + h) * LSEQ + l) * HDIM;
    g_q[obase + d]      = q1 * cc - q2 * s;
    g_q[obase + d + 32] = q2 * cc + q1 * s;
    g_k[obase + d]      = k1 * cc - k2 * s;
    g_k[obase + d + 32] = k2 * cc + k1 * s;
    g_v[obase + d]      = v1;
    g_v[obase + d + 32] = v2;
}

// ---------------------------------------------------------------------------
// Flash attention (causal, online softmax). Unchanged from R1.
// Grid: (L/64, B*H). Block: 64 threads, each owns one q row.
// ---------------------------------------------------------------------------
__global__ void __launch_bounds__(64)
k_flash_attn() {
    __shared__ float Ks[64][68];
    __shared__ float Vs[64][68];

    const int tid = threadIdx.x;
    const int qt  = blockIdx.x;
    const int bh  = blockIdx.y;
    const int qr  = qt * 64 + tid;
    const float scale = 0.125f;

    const float* qptr = g_q + ((size_t)bh * LSEQ + qr) * HDIM;
    float4 q[16];
#pragma unroll
    for (int i = 0; i < 16; i++) q[i] = *(const float4*)(qptr + i * 4);

    float m = -1e30f, l = 0.f;
    float4 o[16];
#pragma unroll
    for (int i = 0; i < 16; i++) o[i] = make_float4(0.f, 0.f, 0.f, 0.f);

    for (int kt = 0; kt <= qt; ++kt) {
        const float* kptr = g_k + ((size_t)bh * LSEQ + kt * 64 + tid) * HDIM;
        const float* vptr = g_v + ((size_t)bh * LSEQ + kt * 64 + tid) * HDIM;
#pragma unroll
        for (int i = 0; i < 16; i++) {
            *(float4*)&Ks[tid][i * 4] = *(const float4*)(kptr + i * 4);
            *(float4*)&Vs[tid][i * 4] = *(const float4*)(vptr + i * 4);
        }
        __syncthreads();

        float s[64];
        float mt = m;
#pragma unroll
        for (int j = 0; j < 64; j++) {
            float acc2 = 0.f;
#pragma unroll
            for (int i = 0; i < 16; i++) {
                float4 kk = *(const float4*)&Ks[j][i * 4];
                acc2 += q[i].x * kk.x + q[i].y * kk.y + q[i].z * kk.z + q[i].w * kk.w;
            }
            acc2 *= scale;
            if (kt == qt && j > tid) acc2 = -1e30f;
            s[j] = acc2;
            mt = fmaxf(mt, acc2);
        }

        float corr = __expf(m - mt);
        m = mt;
        l *= corr;
#pragma unroll
        for (int i = 0; i < 16; i++) {
            o[i].x *= corr; o[i].y *= corr; o[i].z *= corr; o[i].w *= corr;
        }

#pragma unroll
        for (int j = 0; j < 64; j++) {
            float p = __expf(s[j] - m);
            l += p;
#pragma unroll
            for (int i = 0; i < 16; i++) {
                float4 vv = *(const float4*)&Vs[j][i * 4];
                o[i].x += p * vv.x; o[i].y += p * vv.y;
                o[i].z += p * vv.z; o[i].w += p * vv.w;
            }
        }
        __syncthreads();
    }

    const float inv = 1.f / l;
    const int b = bh >> 5, h = bh & 31;
    float* optr = g_ao + ((size_t)(b * LSEQ + qr)) * DMODEL + (size_t)h * HDIM;
#pragma unroll
    for (int i = 0; i < 16; i++) {
        float4 r = make_float4(o[i].x * inv, o[i].y * inv, o[i].z * inv, o[i].w * inv);
        *(float4*)(optr + i * 4) = r;
    }
}

// ---------------------------------------------------------------------------
extern "C" void kernel_launch(void* const* d_in, const int* in_sizes, int n_in,
                              void* d_out, int out_size) {
    const float* x    = (const float*)d_in[0];
    const float* wqkv = (const float*)d_in[1];
    const float* wo   = (const float*)d_in[2];
    float* out        = (float*)d_out;

    float* qkv = nullptr; cudaGetSymbolAddress((void**)&qkv, g_qkv);
    float* ao  = nullptr; cudaGetSymbolAddress((void**)&ao,  g_ao);

    // 1) QKV projection (tf32 tensor cores)
    {
        dim3 grid(NQKV / 128, MROWS / 128);
        k_gemm_tf32<<<grid, 256>>>(x, wqkv, qkv, NQKV, DMODEL);
    }
    // 2) RoPE + split into [B,H,L,hd]
    {
        int total = MROWS * NHEAD * 32;
        k_rope_split<<<(total + 255) / 256, 256>>>();
    }
    // 3) Causal flash attention -> g_ao [B*L, 2048]
    {
        dim3 grid(LSEQ / 64, BSZ * NHEAD);
        k_flash_attn<<<grid, 64>>>();
    }
    // 4) Output projection (tf32 tensor cores)
    {
        dim3 grid(DMODEL / 128, MROWS / 128);
        k_gemm_tf32<<<grid, 256>>>(ao, wo, out, DMODEL, DMODEL);
    }
}

// round 3
// speedup vs baseline: 4.5204x; 2.7564x over previous
#include <cuda_runtime.h>
#include <math.h>
#include <stdint.h>

// Problem constants
#define BSZ 2
#define LSEQ 2048
#define DMODEL 2048
#define NHEAD 32
#define HDIM 64
#define MROWS (BSZ * LSEQ)     // 4096
#define NQKV (3 * DMODEL)      // 6144

// Scratch (device globals; no allocation allowed in kernel_launch)
__device__ float g_qkv[(size_t)MROWS * NQKV];   // [B*L, 3*D]
__device__ float g_q[(size_t)MROWS * DMODEL];   // [B,H,L,hd]
__device__ float g_k[(size_t)MROWS * DMODEL];   // [B,H,L,hd]
__device__ float g_v[(size_t)MROWS * DMODEL];   // [B,H,L,hd]
__device__ float g_ao[(size_t)MROWS * DMODEL];  // [B*L, H*hd]

__device__ __forceinline__ uint32_t f2tf32(float x) {
    uint32_t y;
    asm("cvt.rna.tf32.f32 %0, %1;" : "=r"(y) : "f"(x));
    return y;
}

__device__ __forceinline__ void mma_tf32(float* d, const uint32_t* a,
                                         const uint32_t* b) {
    asm volatile(
        "mma.sync.aligned.m16n8k8.row.col.f32.tf32.tf32.f32 "
        "{%0,%1,%2,%3}, {%4,%5,%6,%7}, {%8,%9}, {%0,%1,%2,%3};"
        : "+f"(d[0]), "+f"(d[1]), "+f"(d[2]), "+f"(d[3])
        : "r"(a[0]), "r"(a[1]), "r"(a[2]), "r"(a[3]), "r"(b[0]), "r"(b[1]));
}

// ---------------------------------------------------------------------------
// TF32 tensor-core GEMM (NT): C[M,N] = A[M,K] @ B[N,K]^T  (unchanged from R2)
// ---------------------------------------------------------------------------
__global__ void __launch_bounds__(256)
k_gemm_tf32(const float* __restrict__ A, const float* __restrict__ B,
            float* __restrict__ C, int N, int K) {
    __shared__ uint32_t As[128][20];
    __shared__ uint32_t Bs[128][20];

    const int tid  = threadIdx.x;
    const int row0 = blockIdx.y * 128;
    const int col0 = blockIdx.x * 128;
    const int warp = tid >> 5, lane = tid & 31;
    const int wr = warp & 1;
    const int wc = warp >> 1;
    const int g  = lane >> 2;
    const int c  = lane & 3;

    float acc[4][4][4];
#pragma unroll
    for (int mt = 0; mt < 4; mt++)
#pragma unroll
        for (int nt = 0; nt < 4; nt++)
#pragma unroll
            for (int i = 0; i < 4; i++) acc[mt][nt][i] = 0.f;

    for (int k0 = 0; k0 < K; k0 += 16) {
#pragma unroll
        for (int i = 0; i < 2; i++) {
            int u  = tid + i * 256;
            int r  = u >> 2;
            int kc = (u & 3) << 2;
            float4 a = *(const float4*)(A + (size_t)(row0 + r) * K + k0 + kc);
            float4 b = *(const float4*)(B + (size_t)(col0 + r) * K + k0 + kc);
            *(uint4*)&As[r][kc] = make_uint4(f2tf32(a.x), f2tf32(a.y), f2tf32(a.z), f2tf32(a.w));
            *(uint4*)&Bs[r][kc] = make_uint4(f2tf32(b.x), f2tf32(b.y), f2tf32(b.z), f2tf32(b.w));
        }
        __syncthreads();

#pragma unroll
        for (int ks = 0; ks < 16; ks += 8) {
            uint32_t af[4][4], bf[4][2];
#pragma unroll
            for (int mt = 0; mt < 4; mt++) {
                int rb = wr * 64 + mt * 16;
                af[mt][0] = As[rb + g][ks + c];
                af[mt][1] = As[rb + g + 8][ks + c];
                af[mt][2] = As[rb + g][ks + c + 4];
                af[mt][3] = As[rb + g + 8][ks + c + 4];
            }
#pragma unroll
            for (int nt = 0; nt < 4; nt++) {
                int cb = wc * 32 + nt * 8;
                bf[nt][0] = Bs[cb + g][ks + c];
                bf[nt][1] = Bs[cb + g][ks + c + 4];
            }
#pragma unroll
            for (int mt = 0; mt < 4; mt++)
#pragma unroll
                for (int nt = 0; nt < 4; nt++)
                    mma_tf32(acc[mt][nt], af[mt], bf[nt]);
        }
        __syncthreads();
    }

#pragma unroll
    for (int mt = 0; mt < 4; mt++) {
        int r0 = row0 + wr * 64 + mt * 16 + g;
#pragma unroll
        for (int nt = 0; nt < 4; nt++) {
            int cc = col0 + wc * 32 + nt * 8 + c * 2;
            *(float2*)&C[(size_t)r0 * N + cc] = make_float2(acc[mt][nt][0], acc[mt][nt][1]);
            *(float2*)&C[(size_t)(r0 + 8) * N + cc] = make_float2(acc[mt][nt][2], acc[mt][nt][3]);
        }
    }
}

// ---------------------------------------------------------------------------
// RoPE + split (unchanged from R2)
// ---------------------------------------------------------------------------
__global__ void __launch_bounds__(256)
k_rope_split() {
    int idx = blockIdx.x * blockDim.x + threadIdx.x;
    const int d  = idx & 31;
    const int h  = (idx >> 5) & 31;
    const int ml = idx >> 10;
    if (ml >= MROWS) return;
    const int l  = ml & (LSEQ - 1);
    const int b  = ml >> 11;

    const size_t base = (size_t)ml * NQKV + (size_t)h * HDIM;
    float q1 = g_qkv[base + d];
    float q2 = g_qkv[base + d + 32];
    float k1 = g_qkv[base + DMODEL + d];
    float k2 = g_qkv[base + DMODEL + d + 32];
    float v1 = g_qkv[base + 2 * DMODEL + d];
    float v2 = g_qkv[base + 2 * DMODEL + d + 32];

    float inv_freq = exp2f(-9.0f * (float)d / 32.0f);
    float f = (float)l * inv_freq;
    float s, cc;
    sincosf(f, &s, &cc);

    const size_t obase = (((size_t)b * NHEAD + h) * LSEQ + l) * HDIM;
    g_q[obase + d]      = q1 * cc - q2 * s;
    g_q[obase + d + 32] = q2 * cc + q1 * s;
    g_k[obase + d]      = k1 * cc - k2 * s;
    g_k[obase + d + 32] = k2 * cc + k1 * s;
    g_v[obase + d]      = v1;
    g_v[obase + d + 32] = v2;
}

// ---------------------------------------------------------------------------
// Tensor-core flash attention (causal, online softmax on mma fragments).
// Grid: (L/64, B*H). Block: 128 threads (4 warps). Q tile 64 rows; warp w owns
// rows [16w, 16w+16). K/V tiles 64x64 staged as tf32 in smem.
// Dynamic smem: Ks[64][68] + Vs[64][68] + Ps[64][68] (Ps doubles as Q staging).
// ---------------------------------------------------------------------------
#define SSTR 68
#define FA_SMEM (3 * 64 * SSTR * 4)

__global__ void __launch_bounds__(128)
k_flash_attn_mma() {
    extern __shared__ uint32_t sm[];
    uint32_t (*Ks)[SSTR] = (uint32_t(*)[SSTR])sm;
    uint32_t (*Vs)[SSTR] = (uint32_t(*)[SSTR])(sm + 64 * SSTR);
    uint32_t (*Ps)[SSTR] = (uint32_t(*)[SSTR])(sm + 2 * 64 * SSTR);
    float    (*Qs)[SSTR] = (float(*)[SSTR])Ps;

    const int tid  = threadIdx.x;
    const int warp = tid >> 5, lane = tid & 31;
    const int g = lane >> 2, c = lane & 3;
    const int qt = blockIdx.x, bh = blockIdx.y;
    const int rb = warp * 16;

    // Stage Q tile (scaled by 1/sqrt(hd), exact power of two) and build A-frags
    {
        const float* Qg = g_q + ((size_t)bh * LSEQ + (size_t)qt * 64) * HDIM;
#pragma unroll
        for (int i = 0; i < 8; i++) {
            int u = tid + i * 128;
            int r = u >> 4, c4 = (u & 15) * 4;
            float4 v = *(const float4*)(Qg + (size_t)r * HDIM + c4);
            Qs[r][c4 + 0] = v.x; Qs[r][c4 + 1] = v.y;
            Qs[r][c4 + 2] = v.z; Qs[r][c4 + 3] = v.w;
        }
    }
    __syncthreads();

    uint32_t af[8][4];
#pragma unroll
    for (int kc = 0; kc < 8; kc++) {
        af[kc][0] = f2tf32(0.125f * Qs[rb + g][kc * 8 + c]);
        af[kc][1] = f2tf32(0.125f * Qs[rb + g + 8][kc * 8 + c]);
        af[kc][2] = f2tf32(0.125f * Qs[rb + g][kc * 8 + c + 4]);
        af[kc][3] = f2tf32(0.125f * Qs[rb + g + 8][kc * 8 + c + 4]);
    }
    __syncthreads();

    float oacc[8][4];
#pragma unroll
    for (int nt = 0; nt < 8; nt++)
#pragma unroll
        for (int i = 0; i < 4; i++) oacc[nt][i] = 0.f;
    float mrow0 = -1e30f, mrow1 = -1e30f;
    float lrow0 = 0.f, lrow1 = 0.f;

    for (int kt = 0; kt <= qt; ++kt) {
        // Stage K and V tiles as tf32
        const float* Kg = g_k + ((size_t)bh * LSEQ + (size_t)kt * 64) * HDIM;
        const float* Vg = g_v + ((size_t)bh * LSEQ + (size_t)kt * 64) * HDIM;
#pragma unroll
        for (int i = 0; i < 8; i++) {
            int u = tid + i * 128;
            int r = u >> 4, c4 = (u & 15) * 4;
            float4 kv = *(const float4*)(Kg + (size_t)r * HDIM + c4);
            float4 vv = *(const float4*)(Vg + (size_t)r * HDIM + c4);
            *(uint4*)&Ks[r][c4] = make_uint4(f2tf32(kv.x), f2tf32(kv.y), f2tf32(kv.z), f2tf32(kv.w));
            *(uint4*)&Vs[r][c4] = make_uint4(f2tf32(vv.x), f2tf32(vv.y), f2tf32(vv.z), f2tf32(vv.w));
        }
        __syncthreads();

        // S = Q @ K^T (scaled)
        float s[8][4];
#pragma unroll
        for (int nt = 0; nt < 8; nt++) {
            s[nt][0] = s[nt][1] = s[nt][2] = s[nt][3] = 0.f;
#pragma unroll
            for (int kc = 0; kc < 8; kc++) {
                uint32_t bf[2];
                bf[0] = Ks[nt * 8 + g][kc * 8 + c];
                bf[1] = Ks[nt * 8 + g][kc * 8 + c + 4];
                mma_tf32(s[nt], af[kc], bf);
            }
        }

        // Causal mask on the diagonal tile
        if (kt == qt) {
#pragma unroll
            for (int nt = 0; nt < 8; nt++) {
                int col0 = nt * 8 + 2 * c;
                if (col0 > rb + g)      s[nt][0] = -1e30f;
                if (col0 + 1 > rb + g)  s[nt][1] = -1e30f;
                if (col0 > rb + g + 8)     s[nt][2] = -1e30f;
                if (col0 + 1 > rb + g + 8) s[nt][3] = -1e30f;
            }
        }

        // Row max (per-thread over cols, then quad reduce)
        float m0 = -1e30f, m1 = -1e30f;
#pragma unroll
        for (int nt = 0; nt < 8; nt++) {
            m0 = fmaxf(m0, fmaxf(s[nt][0], s[nt][1]));
            m1 = fmaxf(m1, fmaxf(s[nt][2], s[nt][3]));
        }
        m0 = fmaxf(m0, __shfl_xor_sync(0xffffffff, m0, 1));
        m0 = fmaxf(m0, __shfl_xor_sync(0xffffffff, m0, 2));
        m1 = fmaxf(m1, __shfl_xor_sync(0xffffffff, m1, 1));
        m1 = fmaxf(m1, __shfl_xor_sync(0xffffffff, m1, 2));
        float newm0 = fmaxf(mrow0, m0);
        float newm1 = fmaxf(mrow1, m1);
        float corr0 = __expf(mrow0 - newm0);
        float corr1 = __expf(mrow1 - newm1);
        mrow0 = newm0; mrow1 = newm1;

#pragma unroll
        for (int nt = 0; nt < 8; nt++) {
            oacc[nt][0] *= corr0; oacc[nt][1] *= corr0;
            oacc[nt][2] *= corr1; oacc[nt][3] *= corr1;
        }
        lrow0 *= corr0; lrow1 *= corr1;

        // P = exp(S - m); accumulate row sums; store P to smem as tf32
#pragma unroll
        for (int nt = 0; nt < 8; nt++) {
            float p0 = __expf(s[nt][0] - newm0);
            float p1 = __expf(s[nt][1] - newm0);
            float p2 = __expf(s[nt][2] - newm1);
            float p3 = __expf(s[nt][3] - newm1);
            lrow0 += p0 + p1;
            lrow1 += p2 + p3;
            Ps[rb + g][nt * 8 + 2 * c]         = f2tf32(p0);
            Ps[rb + g][nt * 8 + 2 * c + 1]     = f2tf32(p1);
            Ps[rb + g + 8][nt * 8 + 2 * c]     = f2tf32(p2);
            Ps[rb + g + 8][nt * 8 + 2 * c + 1] = f2tf32(p3);
        }
        __syncwarp();

        // O += P @ V
#pragma unroll
        for (int kc = 0; kc < 8; kc++) {
            uint32_t pa[4];
            pa[0] = Ps[rb + g][kc * 8 + c];
            pa[1] = Ps[rb + g + 8][kc * 8 + c];
            pa[2] = Ps[rb + g][kc * 8 + c + 4];
            pa[3] = Ps[rb + g + 8][kc * 8 + c + 4];
#pragma unroll
            for (int nt = 0; nt < 8; nt++) {
                uint32_t bf[2];
                bf[0] = Vs[kc * 8 + c][nt * 8 + g];
                bf[1] = Vs[kc * 8 + c + 4][nt * 8 + g];
                mma_tf32(oacc[nt], pa, bf);
            }
        }
        __syncthreads();
    }

    // Final row-sum reduce + normalize + write to g_ao [B*L, H*hd]
    lrow0 += __shfl_xor_sync(0xffffffff, lrow0, 1);
    lrow0 += __shfl_xor_sync(0xffffffff, lrow0, 2);
    lrow1 += __shfl_xor_sync(0xffffffff, lrow1, 1);
    lrow1 += __shfl_xor_sync(0xffffffff, lrow1, 2);
    const float inv0 = 1.f / lrow0;
    const float inv1 = 1.f / lrow1;

    const int b = bh >> 5, h = bh & 31;
    const int qg0 = qt * 64 + rb + g;
    float* o0 = g_ao + ((size_t)(b * LSEQ + qg0)) * DMODEL + (size_t)h * HDIM;
    float* o1 = o0 + (size_t)8 * DMODEL;
#pragma unroll
    for (int nt = 0; nt < 8; nt++) {
        *(float2*)(o0 + nt * 8 + 2 * c) = make_float2(oacc[nt][0] * inv0, oacc[nt][1] * inv0);
        *(float2*)(o1 + nt * 8 + 2 * c) = make_float2(oacc[nt][2] * inv1, oacc[nt][3] * inv1);
    }
}

// ---------------------------------------------------------------------------
extern "C" void kernel_launch(void* const* d_in, const int* in_sizes, int n_in,
                              void* d_out, int out_size) {
    const float* x    = (const float*)d_in[0];
    const float* wqkv = (const float*)d_in[1];
    const float* wo   = (const float*)d_in[2];
    float* out        = (float*)d_out;

    float* qkv = nullptr; cudaGetSymbolAddress((void**)&qkv, g_qkv);
    float* ao  = nullptr; cudaGetSymbolAddress((void**)&ao,  g_ao);

    static bool attr_set = false;
    if (!attr_set) {
        cudaFuncSetAttribute(k_flash_attn_mma,
                             cudaFuncAttributeMaxDynamicSharedMemorySize, FA_SMEM);
        attr_set = true;
    }

    // 1) QKV projection (tf32 tensor cores)
    {
        dim3 grid(NQKV / 128, MROWS / 128);
        k_gemm_tf32<<<grid, 256>>>(x, wqkv, qkv, NQKV, DMODEL);
    }
    // 2) RoPE + split into [B,H,L,hd]
    {
        int total = MROWS * NHEAD * 32;
        k_rope_split<<<(total + 255) / 256, 256>>>();
    }
    // 3) Causal flash attention (tensor cores) -> g_ao
    {
        dim3 grid(LSEQ / 64, BSZ * NHEAD);
        k_flash_attn_mma<<<grid, 128, FA_SMEM>>>();
    }
    // 4) Output projection (tf32 tensor cores)
    {
        dim3 grid(DMODEL / 128, MROWS / 128);
        k_gemm_tf32<<<grid, 256>>>(ao, wo, out, DMODEL, DMODEL);
    }
}

// round 4
// speedup vs baseline: 4.6892x; 1.0373x over previous
#include <cuda_runtime.h>
#include <math.h>
#include <stdint.h>

// Problem constants
#define BSZ 2
#define LSEQ 2048
#define DMODEL 2048
#define NHEAD 32
#define HDIM 64
#define MROWS (BSZ * LSEQ)     // 4096
#define NQKV (3 * DMODEL)      // 6144

// Scratch (device globals)
__device__ float g_qkv[(size_t)MROWS * NQKV];
__device__ float g_q[(size_t)MROWS * DMODEL];   // [B,H,L,hd]
__device__ float g_k[(size_t)MROWS * DMODEL];   // [B,H,L,hd]
__device__ float g_v[(size_t)MROWS * DMODEL];   // [B,H,L,hd]
__device__ float g_ao[(size_t)MROWS * DMODEL];  // [B*L, H*hd]

__device__ __forceinline__ uint32_t f2tf32(float x) {
    uint32_t y;
    asm("cvt.rna.tf32.f32 %0, %1;" : "=r"(y) : "f"(x));
    return y;
}
__device__ __forceinline__ float ex2f(float x) {
    float y;
    asm("ex2.approx.f32 %0, %1;" : "=f"(y) : "f"(x));
    return y;
}
__device__ __forceinline__ void mma_tf32(float* d, const uint32_t* a,
                                         const uint32_t* b) {
    asm volatile(
        "mma.sync.aligned.m16n8k8.row.col.f32.tf32.tf32.f32 "
        "{%0,%1,%2,%3}, {%4,%5,%6,%7}, {%8,%9}, {%0,%1,%2,%3};"
        : "+f"(d[0]), "+f"(d[1]), "+f"(d[2]), "+f"(d[3])
        : "r"(a[0]), "r"(a[1]), "r"(a[2]), "r"(a[3]), "r"(b[0]), "r"(b[1]));
}

// ---------------------------------------------------------------------------
// TF32 tensor-core GEMM (NT): C[M,N] = A[M,K] @ B[N,K]^T  (unchanged)
// ---------------------------------------------------------------------------
__global__ void __launch_bounds__(256)
k_gemm_tf32(const float* __restrict__ A, const float* __restrict__ B,
            float* __restrict__ C, int N, int K) {
    __shared__ uint32_t As[128][20];
    __shared__ uint32_t Bs[128][20];

    const int tid  = threadIdx.x;
    const int row0 = blockIdx.y * 128;
    const int col0 = blockIdx.x * 128;
    const int warp = tid >> 5, lane = tid & 31;
    const int wr = warp & 1;
    const int wc = warp >> 1;
    const int g  = lane >> 2;
    const int c  = lane & 3;

    float acc[4][4][4];
#pragma unroll
    for (int mt = 0; mt < 4; mt++)
#pragma unroll
        for (int nt = 0; nt < 4; nt++)
#pragma unroll
            for (int i = 0; i < 4; i++) acc[mt][nt][i] = 0.f;

    for (int k0 = 0; k0 < K; k0 += 16) {
#pragma unroll
        for (int i = 0; i < 2; i++) {
            int u  = tid + i * 256;
            int r  = u >> 2;
            int kc = (u & 3) << 2;
            float4 a = *(const float4*)(A + (size_t)(row0 + r) * K + k0 + kc);
            float4 b = *(const float4*)(B + (size_t)(col0 + r) * K + k0 + kc);
            *(uint4*)&As[r][kc] = make_uint4(f2tf32(a.x), f2tf32(a.y), f2tf32(a.z), f2tf32(a.w));
            *(uint4*)&Bs[r][kc] = make_uint4(f2tf32(b.x), f2tf32(b.y), f2tf32(b.z), f2tf32(b.w));
        }
        __syncthreads();

#pragma unroll
        for (int ks = 0; ks < 16; ks += 8) {
            uint32_t af[4][4], bf[4][2];
#pragma unroll
            for (int mt = 0; mt < 4; mt++) {
                int rb = wr * 64 + mt * 16;
                af[mt][0] = As[rb + g][ks + c];
                af[mt][1] = As[rb + g + 8][ks + c];
                af[mt][2] = As[rb + g][ks + c + 4];
                af[mt][3] = As[rb + g + 8][ks + c + 4];
            }
#pragma unroll
            for (int nt = 0; nt < 4; nt++) {
                int cb = wc * 32 + nt * 8;
                bf[nt][0] = Bs[cb + g][ks + c];
                bf[nt][1] = Bs[cb + g][ks + c + 4];
            }
#pragma unroll
            for (int mt = 0; mt < 4; mt++)
#pragma unroll
                for (int nt = 0; nt < 4; nt++)
                    mma_tf32(acc[mt][nt], af[mt], bf[nt]);
        }
        __syncthreads();
    }

#pragma unroll
    for (int mt = 0; mt < 4; mt++) {
        int r0 = row0 + wr * 64 + mt * 16 + g;
#pragma unroll
        for (int nt = 0; nt < 4; nt++) {
            int cc = col0 + wc * 32 + nt * 8 + c * 2;
            *(float2*)&C[(size_t)r0 * N + cc] = make_float2(acc[mt][nt][0], acc[mt][nt][1]);
            *(float2*)&C[(size_t)(r0 + 8) * N + cc] = make_float2(acc[mt][nt][2], acc[mt][nt][3]);
        }
    }
}

// ---------------------------------------------------------------------------
// RoPE + split (unchanged)
// ---------------------------------------------------------------------------
__global__ void __launch_bounds__(256)
k_rope_split() {
    int idx = blockIdx.x * blockDim.x + threadIdx.x;
    const int d  = idx & 31;
    const int h  = (idx >> 5) & 31;
    const int ml = idx >> 10;
    if (ml >= MROWS) return;
    const int l  = ml & (LSEQ - 1);
    const int b  = ml >> 11;

    const size_t base = (size_t)ml * NQKV + (size_t)h * HDIM;
    float q1 = g_qkv[base + d];
    float q2 = g_qkv[base + d + 32];
    float k1 = g_qkv[base + DMODEL + d];
    float k2 = g_qkv[base + DMODEL + d + 32];
    float v1 = g_qkv[base + 2 * DMODEL + d];
    float v2 = g_qkv[base + 2 * DMODEL + d + 32];

    float inv_freq = exp2f(-9.0f * (float)d / 32.0f);
    float f = (float)l * inv_freq;
    float s, cc;
    sincosf(f, &s, &cc);

    const size_t obase = (((size_t)b * NHEAD + h) * LSEQ + l) * HDIM;
    g_q[obase + d]      = q1 * cc - q2 * s;
    g_q[obase + d + 32] = q2 * cc + q1 * s;
    g_k[obase + d]      = k1 * cc - k2 * s;
    g_k[obase + d + 32] = k2 * cc + k1 * s;
    g_v[obase + d]      = v1;
    g_v[obase + d + 32] = v2;
}

// ---------------------------------------------------------------------------
// Tensor-core flash attention v2.
// Grid: (L/128, B*H). Block: 256 threads (8 warps); warp w owns Q rows
// [16w,16w+16). K-permutation: mma k-slots (c,c+4) <-> indices (2c,2c+1), so
// QK/PV B-frags are single LDS.64 and P stays in registers (accumulator layout
// == permuted A-frag layout). V staged transposed. Stride 72 (== 8 mod 32)
// makes all 64-bit fragment loads conflict-free per half-warp phase.
// ---------------------------------------------------------------------------
#define KSTR 72
#define FA_SMEM ((128 * KSTR + 2 * 64 * KSTR) * 4)

__global__ void __launch_bounds__(256)
k_flash_attn_mma() {
    extern __shared__ uint32_t sm[];
    float    (*Qs)[KSTR] = (float(*)[KSTR])sm;                   // 128 x 72
    uint32_t (*Ks)[KSTR] = (uint32_t(*)[KSTR])(sm + 128 * KSTR); // 64 x 72
    uint32_t (*Vt)[KSTR] = (uint32_t(*)[KSTR])(sm + 192 * KSTR); // 64 x 72 (transposed)

    const int tid  = threadIdx.x;
    const int warp = tid >> 5, lane = tid & 31;
    const int g = lane >> 2, c = lane & 3;
    const int qt = blockIdx.x, bh = blockIdx.y;
    const int rb = warp * 16;
    const float qscale = 0.125f * 1.4426950408889634f;  // 1/sqrt(hd) * log2(e)

    // Stage Q tile (128 x 64)
    const float* Qg = g_q + ((size_t)bh * LSEQ + (size_t)qt * 128) * HDIM;
#pragma unroll
    for (int i = 0; i < 8; i++) {
        int u = tid + i * 256;
        int r = u >> 4, c4 = (u & 15) * 4;
        *(float4*)&Qs[r][c4] = *(const float4*)(Qg + (size_t)r * HDIM + c4);
    }
    __syncthreads();

    // A-frags with k-permutation: af[kc] = Q[g / g+8][8kc+2c / +1], pre-scaled
    uint32_t af[8][4];
#pragma unroll
    for (int kc = 0; kc < 8; kc++) {
        float2 a0 = *(const float2*)&Qs[rb + g][kc * 8 + 2 * c];
        float2 a1 = *(const float2*)&Qs[rb + g + 8][kc * 8 + 2 * c];
        af[kc][0] = f2tf32(qscale * a0.x);
        af[kc][2] = f2tf32(qscale * a0.y);
        af[kc][1] = f2tf32(qscale * a1.x);
        af[kc][3] = f2tf32(qscale * a1.y);
    }

    float oacc[8][4];
#pragma unroll
    for (int nt = 0; nt < 8; nt++)
#pragma unroll
        for (int i = 0; i < 4; i++) oacc[nt][i] = 0.f;
    float m0 = -1e30f, m1 = -1e30f, l0 = 0.f, l1 = 0.f;

    const int ktmax = 2 * qt + 1;
    for (int kt = 0; kt <= ktmax; ++kt) {
        __syncthreads();  // previous iteration's reads of Ks/Vt complete
        // Stage K row-major (rows = kv, cols = hd)
        const float* Kg = g_k + ((size_t)bh * LSEQ + (size_t)kt * 64) * HDIM;
#pragma unroll
        for (int i = 0; i < 4; i++) {
            int u = tid + i * 256;
            int r = u >> 4, c4 = (u & 15) * 4;
            float4 kv = *(const float4*)(Kg + (size_t)r * HDIM + c4);
            *(uint4*)&Ks[r][c4] =
                make_uint4(f2tf32(kv.x), f2tf32(kv.y), f2tf32(kv.z), f2tf32(kv.w));
        }
        // Stage V transposed: Vt[hd col][kv row]
        const float* Vg = g_v + ((size_t)bh * LSEQ + (size_t)kt * 64) * HDIM;
        {
            int col = tid & 63;
            int r0  = (tid >> 6) * 4;
#pragma unroll
            for (int i = 0; i < 4; i++) {
                int r = r0 + i * 16;
                uint4 w;
                w.x = f2tf32(Vg[(size_t)(r + 0) * HDIM + col]);
                w.y = f2tf32(Vg[(size_t)(r + 1) * HDIM + col]);
                w.z = f2tf32(Vg[(size_t)(r + 2) * HDIM + col]);
                w.w = f2tf32(Vg[(size_t)(r + 3) * HDIM + col]);
                *(uint4*)&Vt[col][r] = w;
            }
        }
        __syncthreads();

        // S = Q @ K^T (in log2 domain via pre-scaled Q)
        float s[8][4];
#pragma unroll
        for (int nt = 0; nt < 8; nt++) {
            s[nt][0] = s[nt][1] = s[nt][2] = s[nt][3] = 0.f;
#pragma unroll
            for (int kc = 0; kc < 8; kc++) {
                uint2 b = *(const uint2*)&Ks[nt * 8 + g][kc * 8 + 2 * c];
                uint32_t bf[2] = {b.x, b.y};
                mma_tf32(s[nt], af[kc], bf);
            }
        }

        // Causal mask (only the two diagonal-adjacent tiles can be masked)
        if (kt >= 2 * qt) {
            int qr0 = qt * 128 + rb + g;
            int qr1 = qr0 + 8;
#pragma unroll
            for (int nt = 0; nt < 8; nt++) {
                int col = kt * 64 + nt * 8 + 2 * c;
                if (col > qr0)     s[nt][0] = -1e30f;
                if (col + 1 > qr0) s[nt][1] = -1e30f;
                if (col > qr1)     s[nt][2] = -1e30f;
                if (col + 1 > qr1) s[nt][3] = -1e30f;
            }
        }

        // Online softmax (base-2)
        float tm0 = -1e30f, tm1 = -1e30f;
#pragma unroll
        for (int nt = 0; nt < 8; nt++) {
            tm0 = fmaxf(tm0, fmaxf(s[nt][0], s[nt][1]));
            tm1 = fmaxf(tm1, fmaxf(s[nt][2], s[nt][3]));
        }
        tm0 = fmaxf(tm0, __shfl_xor_sync(0xffffffff, tm0, 1));
        tm0 = fmaxf(tm0, __shfl_xor_sync(0xffffffff, tm0, 2));
        tm1 = fmaxf(tm1, __shfl_xor_sync(0xffffffff, tm1, 1));
        tm1 = fmaxf(tm1, __shfl_xor_sync(0xffffffff, tm1, 2));
        float nm0 = fmaxf(m0, tm0);
        float nm1 = fmaxf(m1, tm1);
        float cr0 = ex2f(m0 - nm0);
        float cr1 = ex2f(m1 - nm1);
        m0 = nm0; m1 = nm1;
        l0 *= cr0; l1 *= cr1;
#pragma unroll
        for (int nt = 0; nt < 8; nt++) {
            oacc[nt][0] *= cr0; oacc[nt][1] *= cr0;
            oacc[nt][2] *= cr1; oacc[nt][3] *= cr1;
        }
#pragma unroll
        for (int nt = 0; nt < 8; nt++) {
            s[nt][0] = ex2f(s[nt][0] - nm0);
            s[nt][1] = ex2f(s[nt][1] - nm0);
            s[nt][2] = ex2f(s[nt][2] - nm1);
            s[nt][3] = ex2f(s[nt][3] - nm1);
            l0 += s[nt][0] + s[nt][1];
            l1 += s[nt][2] + s[nt][3];
        }

        // O += P @ V : P already in A-frag layout (k-permuted), V from Vt
#pragma unroll
        for (int kc = 0; kc < 8; kc++) {
            uint32_t pa[4];
            pa[0] = f2tf32(s[kc][0]);
            pa[1] = f2tf32(s[kc][2]);
            pa[2] = f2tf32(s[kc][1]);
            pa[3] = f2tf32(s[kc][3]);
#pragma unroll
            for (int nt = 0; nt < 8; nt++) {
                uint2 b = *(const uint2*)&Vt[nt * 8 + g][kc * 8 + 2 * c];
                uint32_t bf[2] = {b.x, b.y};
                mma_tf32(oacc[nt], pa, bf);
            }
        }
    }

    // Reduce row sums, normalize, write out
    l0 += __shfl_xor_sync(0xffffffff, l0, 1);
    l0 += __shfl_xor_sync(0xffffffff, l0, 2);
    l1 += __shfl_xor_sync(0xffffffff, l1, 1);
    l1 += __shfl_xor_sync(0xffffffff, l1, 2);
    const float inv0 = 1.f / l0;
    const float inv1 = 1.f / l1;

    const int b = bh >> 5, h = bh & 31;
    const int qr = qt * 128 + rb + g;
    float* o0 = g_ao + ((size_t)(b * LSEQ + qr)) * DMODEL + (size_t)h * HDIM;
    float* o1 = o0 + (size_t)8 * DMODEL;
#pragma unroll
    for (int nt = 0; nt < 8; nt++) {
        *(float2*)(o0 + nt * 8 + 2 * c) = make_float2(oacc[nt][0] * inv0, oacc[nt][1] * inv0);
        *(float2*)(o1 + nt * 8 + 2 * c) = make_float2(oacc[nt][2] * inv1, oacc[nt][3] * inv1);
    }
}

// ---------------------------------------------------------------------------
extern "C" void kernel_launch(void* const* d_in, const int* in_sizes, int n_in,
                              void* d_out, int out_size) {
    const float* x    = (const float*)d_in[0];
    const float* wqkv = (const float*)d_in[1];
    const float* wo   = (const float*)d_in[2];
    float* out        = (float*)d_out;

    float* qkv = nullptr; cudaGetSymbolAddress((void**)&qkv, g_qkv);
    float* ao  = nullptr; cudaGetSymbolAddress((void**)&ao,  g_ao);

    static bool attr_set = false;
    if (!attr_set) {
        cudaFuncSetAttribute(k_flash_attn_mma,
                             cudaFuncAttributeMaxDynamicSharedMemorySize, FA_SMEM);
        attr_set = true;
    }

    // 1) QKV projection
    {
        dim3 grid(NQKV / 128, MROWS / 128);
        k_gemm_tf32<<<grid, 256>>>(x, wqkv, qkv, NQKV, DMODEL);
    }
    // 2) RoPE + split
    {
        int total = MROWS * NHEAD * 32;
        k_rope_split<<<(total + 255) / 256, 256>>>();
    }
    // 3) Flash attention
    {
        dim3 grid(LSEQ / 128, BSZ * NHEAD);
        k_flash_attn_mma<<<grid, 256, FA_SMEM>>>();
    }
    // 4) Output projection
    {
        dim3 grid(DMODEL / 128, MROWS / 128);
        k_gemm_tf32<<<grid, 256>>>(ao, wo, out, DMODEL, DMODEL);
    }
}

// round 5
// speedup vs baseline: 4.7354x; 1.0099x over previous
#include <cuda_runtime.h>
#include <math.h>
#include <stdint.h>

// Problem constants
#define BSZ 2
#define LSEQ 2048
#define DMODEL 2048
#define NHEAD 32
#define HDIM 64
#define MROWS (BSZ * LSEQ)     // 4096
#define NQKV (3 * DMODEL)      // 6144

// Scratch (device globals)
__device__ float g_qkv[(size_t)MROWS * NQKV];
__device__ float g_q[(size_t)MROWS * DMODEL];   // [B,H,L,hd]
__device__ float g_k[(size_t)MROWS * DMODEL];   // [B,H,L,hd]
__device__ float g_v[(size_t)MROWS * DMODEL];   // [B,H,L,hd]
__device__ float g_ao[(size_t)MROWS * DMODEL];  // [B*L, H*hd]

__device__ __forceinline__ uint32_t f2tf32(float x) {
    uint32_t y;
    asm("cvt.rna.tf32.f32 %0, %1;" : "=r"(y) : "f"(x));
    return y;
}
__device__ __forceinline__ float ex2f(float x) {
    float y;
    asm("ex2.approx.f32 %0, %1;" : "=f"(y) : "f"(x));
    return y;
}
__device__ __forceinline__ void mma_tf32(float* d, const uint32_t* a,
                                         const uint32_t* b) {
    asm volatile(
        "mma.sync.aligned.m16n8k8.row.col.f32.tf32.tf32.f32 "
        "{%0,%1,%2,%3}, {%4,%5,%6,%7}, {%8,%9}, {%0,%1,%2,%3};"
        : "+f"(d[0]), "+f"(d[1]), "+f"(d[2]), "+f"(d[3])
        : "r"(a[0]), "r"(a[1]), "r"(a[2]), "r"(a[3]), "r"(b[0]), "r"(b[1]));
}
__device__ __forceinline__ uint32_t sm_u32(const void* p) {
    uint32_t a;
    asm("{ .reg .u64 t; cvta.to.shared.u64 t, %1; cvt.u32.u64 %0, t; }"
        : "=r"(a) : "l"(p));
    return a;
}
__device__ __forceinline__ void cp16(uint32_t dst, const void* src) {
    asm volatile("cp.async.cg.shared.global [%0], [%1], 16;" :: "r"(dst), "l"(src));
}
#define CP_COMMIT() asm volatile("cp.async.commit_group;")
#define CP_WAIT0()  asm volatile("cp.async.wait_group 0;")

// ---------------------------------------------------------------------------
// TF32 tensor-core GEMM (NT): C[M,N] = A[M,K] @ B[N,K]^T  (unchanged)
// ---------------------------------------------------------------------------
__global__ void __launch_bounds__(256)
k_gemm_tf32(const float* __restrict__ A, const float* __restrict__ B,
            float* __restrict__ C, int N, int K) {
    __shared__ uint32_t As[128][20];
    __shared__ uint32_t Bs[128][20];

    const int tid  = threadIdx.x;
    const int row0 = blockIdx.y * 128;
    const int col0 = blockIdx.x * 128;
    const int warp = tid >> 5, lane = tid & 31;
    const int wr = warp & 1;
    const int wc = warp >> 1;
    const int g  = lane >> 2;
    const int c  = lane & 3;

    float acc[4][4][4];
#pragma unroll
    for (int mt = 0; mt < 4; mt++)
#pragma unroll
        for (int nt = 0; nt < 4; nt++)
#pragma unroll
            for (int i = 0; i < 4; i++) acc[mt][nt][i] = 0.f;

    for (int k0 = 0; k0 < K; k0 += 16) {
#pragma unroll
        for (int i = 0; i < 2; i++) {
            int u  = tid + i * 256;
            int r  = u >> 2;
            int kc = (u & 3) << 2;
            float4 a = *(const float4*)(A + (size_t)(row0 + r) * K + k0 + kc);
            float4 b = *(const float4*)(B + (size_t)(col0 + r) * K + k0 + kc);
            *(uint4*)&As[r][kc] = make_uint4(f2tf32(a.x), f2tf32(a.y), f2tf32(a.z), f2tf32(a.w));
            *(uint4*)&Bs[r][kc] = make_uint4(f2tf32(b.x), f2tf32(b.y), f2tf32(b.z), f2tf32(b.w));
        }
        __syncthreads();

#pragma unroll
        for (int ks = 0; ks < 16; ks += 8) {
            uint32_t af[4][4], bf[4][2];
#pragma unroll
            for (int mt = 0; mt < 4; mt++) {
                int rb = wr * 64 + mt * 16;
                af[mt][0] = As[rb + g][ks + c];
                af[mt][1] = As[rb + g + 8][ks + c];
                af[mt][2] = As[rb + g][ks + c + 4];
                af[mt][3] = As[rb + g + 8][ks + c + 4];
            }
#pragma unroll
            for (int nt = 0; nt < 4; nt++) {
                int cb = wc * 32 + nt * 8;
                bf[nt][0] = Bs[cb + g][ks + c];
                bf[nt][1] = Bs[cb + g][ks + c + 4];
            }
#pragma unroll
            for (int mt = 0; mt < 4; mt++)
#pragma unroll
                for (int nt = 0; nt < 4; nt++)
                    mma_tf32(acc[mt][nt], af[mt], bf[nt]);
        }
        __syncthreads();
    }

#pragma unroll
    for (int mt = 0; mt < 4; mt++) {
        int r0 = row0 + wr * 64 + mt * 16 + g;
#pragma unroll
        for (int nt = 0; nt < 4; nt++) {
            int cc = col0 + wc * 32 + nt * 8 + c * 2;
            *(float2*)&C[(size_t)r0 * N + cc] = make_float2(acc[mt][nt][0], acc[mt][nt][1]);
            *(float2*)&C[(size_t)(r0 + 8) * N + cc] = make_float2(acc[mt][nt][2], acc[mt][nt][3]);
        }
    }
}

// ---------------------------------------------------------------------------
// RoPE + split (unchanged)
// ---------------------------------------------------------------------------
__global__ void __launch_bounds__(256)
k_rope_split() {
    int idx = blockIdx.x * blockDim.x + threadIdx.x;
    const int d  = idx & 31;
    const int h  = (idx >> 5) & 31;
    const int ml = idx >> 10;
    if (ml >= MROWS) return;
    const int l  = ml & (LSEQ - 1);
    const int b  = ml >> 11;

    const size_t base = (size_t)ml * NQKV + (size_t)h * HDIM;
    float q1 = g_qkv[base + d];
    float q2 = g_qkv[base + d + 32];
    float k1 = g_qkv[base + DMODEL + d];
    float k2 = g_qkv[base + DMODEL + d + 32];
    float v1 = g_qkv[base + 2 * DMODEL + d];
    float v2 = g_qkv[base + 2 * DMODEL + d + 32];

    float inv_freq = exp2f(-9.0f * (float)d / 32.0f);
    float f = (float)l * inv_freq;
    float s, cc;
    sincosf(f, &s, &cc);

    const size_t obase = (((size_t)b * NHEAD + h) * LSEQ + l) * HDIM;
    g_q[obase + d]      = q1 * cc - q2 * s;
    g_q[obase + d + 32] = q2 * cc + q1 * s;
    g_k[obase + d]      = k1 * cc - k2 * s;
    g_k[obase + d + 32] = k2 * cc + k1 * s;
    g_v[obase + d]      = v1;
    g_v[obase + d + 32] = v2;
}

// ---------------------------------------------------------------------------
// Tensor-core flash attention v3: cp.async double-buffered K/V pipeline.
// Grid: (L/128, B*H). Block: 256 threads / 8 warps; warp w owns Q rows
// [16w,16w+16). K-permutation as in v2 (P stays in registers).
// smem (words): Ks[2] @0 (2*64*72), Vt[2] @9216 (2*64*72), Vraw[2] @18432
// (2*64*68). Q staging aliases Ks[0..1] (dead after prologue).
// ---------------------------------------------------------------------------
#define KSTR 72
#define VRSTR 68
#define FA_WORDS (4 * 64 * KSTR + 2 * 64 * VRSTR)   // 27136 words
#define FA_SMEM (FA_WORDS * 4)                       // 108544 B

__global__ void __launch_bounds__(256)
k_flash_attn_mma() {
    extern __shared__ uint32_t sm[];

    const int tid  = threadIdx.x;
    const int warp = tid >> 5, lane = tid & 31;
    const int g = lane >> 2, c = lane & 3;
    const int qt = gridDim.x - 1 - blockIdx.x;   // big blocks first
    const int bh = blockIdx.y;
    const int rb = warp * 16;
    const float qscale = 0.125f * 1.4426950408889634f;  // 1/sqrt(hd) * log2(e)

    const uint32_t smb = sm_u32(sm);

    // ---- Prologue: stage Q (aliases Ks region), build A-frags -------------
    float (*Qs)[KSTR] = (float(*)[KSTR])sm;      // 128 x 72, aliases Ks[0..1]
    const float* Qg = g_q + ((size_t)bh * LSEQ + (size_t)qt * 128) * HDIM;
#pragma unroll
    for (int i = 0; i < 8; i++) {
        int u = tid + i * 256;
        int r = u >> 4, c4 = (u & 15) * 4;
        *(float4*)&Qs[r][c4] = *(const float4*)(Qg + (size_t)r * HDIM + c4);
    }
    __syncthreads();

    uint32_t af[8][4];
#pragma unroll
    for (int kc = 0; kc < 8; kc++) {
        float2 a0 = *(const float2*)&Qs[rb + g][kc * 8 + 2 * c];
        float2 a1 = *(const float2*)&Qs[rb + g + 8][kc * 8 + 2 * c];
        af[kc][0] = f2tf32(qscale * a0.x);
        af[kc][2] = f2tf32(qscale * a0.y);
        af[kc][1] = f2tf32(qscale * a1.x);
        af[kc][3] = f2tf32(qscale * a1.y);
    }
    __syncthreads();   // Q region is now dead; safe to overwrite with K

    // Per-thread copy geometry (same mapping for cp.async and K-convert)
    const int cp_r  = tid >> 4;          // +16 per i
    const int cp_c4 = (tid & 15) * 4;
    const int tv_col = tid & 63;         // V transpose
    const int tv_r0  = (tid >> 6) * 4;

    const float* Kg0 = g_k + (size_t)bh * LSEQ * HDIM;
    const float* Vg0 = g_v + (size_t)bh * LSEQ * HDIM;

    // ---- issue cp.async for tile 0 into buffer 0 ---------------------------
    {
        const float* Kg = Kg0;
        const float* Vg = Vg0;
        uint32_t ks = smb;                                  // Ks[0]
        uint32_t vr = smb + (256 * KSTR) * 4;               // Vraw[0]
#pragma unroll
        for (int i = 0; i < 4; i++) {
            int r = cp_r + i * 16;
            cp16(ks + (r * KSTR + cp_c4) * 4, Kg + (size_t)r * HDIM + cp_c4);
            cp16(vr + (r * VRSTR + cp_c4) * 4, Vg + (size_t)r * HDIM + cp_c4);
        }
        CP_COMMIT();
        CP_WAIT0();
        __syncthreads();
        // convert K in place (own chunks), transpose+convert V
        uint32_t (*Kb)[KSTR]  = (uint32_t(*)[KSTR])sm;
        float    (*Vr)[VRSTR] = (float(*)[VRSTR])(sm + 256 * KSTR);
        uint32_t (*Vtb)[KSTR] = (uint32_t(*)[KSTR])(sm + 128 * KSTR);
#pragma unroll
        for (int i = 0; i < 4; i++) {
            int r = cp_r + i * 16;
            float4 v = *(float4*)&Kb[r][cp_c4];
            *(uint4*)&Kb[r][cp_c4] = make_uint4(f2tf32(v.x), f2tf32(v.y), f2tf32(v.z), f2tf32(v.w));
        }
#pragma unroll
        for (int i = 0; i < 4; i++) {
            int r = tv_r0 + i * 16;
            uint4 w = make_uint4(f2tf32(Vr[r + 0][tv_col]), f2tf32(Vr[r + 1][tv_col]),
                                 f2tf32(Vr[r + 2][tv_col]), f2tf32(Vr[r + 3][tv_col]));
            *(uint4*)&Vtb[tv_col][r] = w;
        }
        __syncthreads();
    }

    float oacc[8][4];
#pragma unroll
    for (int nt = 0; nt < 8; nt++)
#pragma unroll
        for (int i = 0; i < 4; i++) oacc[nt][i] = 0.f;
    float m0 = -1e30f, m1 = -1e30f, l0 = 0.f, l1 = 0.f;

    const int ktmax = 2 * qt + 1;
    for (int kt = 0; kt <= ktmax; ++kt) {
        const int b = kt & 1;

        // Prefetch next tile into the other buffer (raw bits)
        if (kt < ktmax) {
            const float* Kg = Kg0 + (size_t)(kt + 1) * 64 * HDIM;
            const float* Vg = Vg0 + (size_t)(kt + 1) * 64 * HDIM;
            uint32_t ks = smb + ((b ^ 1) * 64 * KSTR) * 4;
            uint32_t vr = smb + (256 * KSTR + (b ^ 1) * 64 * VRSTR) * 4;
#pragma unroll
            for (int i = 0; i < 4; i++) {
                int r = cp_r + i * 16;
                cp16(ks + (r * KSTR + cp_c4) * 4, Kg + (size_t)r * HDIM + cp_c4);
                cp16(vr + (r * VRSTR + cp_c4) * 4, Vg + (size_t)r * HDIM + cp_c4);
            }
            CP_COMMIT();
        }

        uint32_t (*Ks)[KSTR] = (uint32_t(*)[KSTR])(sm + b * 64 * KSTR);
        uint32_t (*Vt)[KSTR] = (uint32_t(*)[KSTR])(sm + (128 + b * 64) * KSTR);

        // S = Q @ K^T (log2 domain via pre-scaled Q)
        float s[8][4];
#pragma unroll
        for (int nt = 0; nt < 8; nt++) {
            s[nt][0] = s[nt][1] = s[nt][2] = s[nt][3] = 0.f;
#pragma unroll
            for (int kc = 0; kc < 8; kc++) {
                uint2 bb = *(const uint2*)&Ks[nt * 8 + g][kc * 8 + 2 * c];
                uint32_t bf[2] = {bb.x, bb.y};
                mma_tf32(s[nt], af[kc], bf);
            }
        }

        // Causal mask (only diagonal-adjacent tiles)
        if (kt >= 2 * qt) {
            int qr0 = qt * 128 + rb + g;
            int qr1 = qr0 + 8;
#pragma unroll
            for (int nt = 0; nt < 8; nt++) {
                int col = kt * 64 + nt * 8 + 2 * c;
                if (col > qr0)     s[nt][0] = -1e30f;
                if (col + 1 > qr0) s[nt][1] = -1e30f;
                if (col > qr1)     s[nt][2] = -1e30f;
                if (col + 1 > qr1) s[nt][3] = -1e30f;
            }
        }

        // Online softmax (base-2)
        float tm0 = -1e30f, tm1 = -1e30f;
#pragma unroll
        for (int nt = 0; nt < 8; nt++) {
            tm0 = fmaxf(tm0, fmaxf(s[nt][0], s[nt][1]));
            tm1 = fmaxf(tm1, fmaxf(s[nt][2], s[nt][3]));
        }
        tm0 = fmaxf(tm0, __shfl_xor_sync(0xffffffff, tm0, 1));
        tm0 = fmaxf(tm0, __shfl_xor_sync(0xffffffff, tm0, 2));
        tm1 = fmaxf(tm1, __shfl_xor_sync(0xffffffff, tm1, 1));
        tm1 = fmaxf(tm1, __shfl_xor_sync(0xffffffff, tm1, 2));
        float nm0 = fmaxf(m0, tm0);
        float nm1 = fmaxf(m1, tm1);
        float cr0 = ex2f(m0 - nm0);
        float cr1 = ex2f(m1 - nm1);
        m0 = nm0; m1 = nm1;
        l0 *= cr0; l1 *= cr1;
#pragma unroll
        for (int nt = 0; nt < 8; nt++) {
            oacc[nt][0] *= cr0; oacc[nt][1] *= cr0;
            oacc[nt][2] *= cr1; oacc[nt][3] *= cr1;
        }
#pragma unroll
        for (int nt = 0; nt < 8; nt++) {
            s[nt][0] = ex2f(s[nt][0] - nm0);
            s[nt][1] = ex2f(s[nt][1] - nm0);
            s[nt][2] = ex2f(s[nt][2] - nm1);
            s[nt][3] = ex2f(s[nt][3] - nm1);
            l0 += s[nt][0] + s[nt][1];
            l1 += s[nt][2] + s[nt][3];
        }

        // O += P @ V  (P in registers, k-permuted layout)
#pragma unroll
        for (int kc = 0; kc < 8; kc++) {
            uint32_t pa[4];
            pa[0] = f2tf32(s[kc][0]);
            pa[1] = f2tf32(s[kc][2]);
            pa[2] = f2tf32(s[kc][1]);
            pa[3] = f2tf32(s[kc][3]);
#pragma unroll
            for (int nt = 0; nt < 8; nt++) {
                uint2 bb = *(const uint2*)&Vt[nt * 8 + g][kc * 8 + 2 * c];
                uint32_t bf[2] = {bb.x, bb.y};
                mma_tf32(oacc[nt], pa, bf);
            }
        }

        // Make next tile mma-ready (data already local: smem-only passes)
        if (kt < ktmax) {
            CP_WAIT0();
            __syncthreads();   // all threads' copies visible; compute(b) done
            uint32_t (*Kb)[KSTR]  = (uint32_t(*)[KSTR])(sm + (b ^ 1) * 64 * KSTR);
            float    (*Vr)[VRSTR] = (float(*)[VRSTR])(sm + 256 * KSTR + (b ^ 1) * 64 * VRSTR);
            uint32_t (*Vtb)[KSTR] = (uint32_t(*)[KSTR])(sm + (128 + (b ^ 1) * 64) * KSTR);
#pragma unroll
            for (int i = 0; i < 4; i++) {
                int r = cp_r + i * 16;
                float4 v = *(float4*)&Kb[r][cp_c4];
                *(uint4*)&Kb[r][cp_c4] = make_uint4(f2tf32(v.x), f2tf32(v.y), f2tf32(v.z), f2tf32(v.w));
            }
#pragma unroll
            for (int i = 0; i < 4; i++) {
                int r = tv_r0 + i * 16;
                uint4 w = make_uint4(f2tf32(Vr[r + 0][tv_col]), f2tf32(Vr[r + 1][tv_col]),
                                     f2tf32(Vr[r + 2][tv_col]), f2tf32(Vr[r + 3][tv_col]));
                *(uint4*)&Vtb[tv_col][r] = w;
            }
            __syncthreads();
        }
    }

    // Reduce row sums, normalize, write out
    l0 += __shfl_xor_sync(0xffffffff, l0, 1);
    l0 += __shfl_xor_sync(0xffffffff, l0, 2);
    l1 += __shfl_xor_sync(0xffffffff, l1, 1);
    l1 += __shfl_xor_sync(0xffffffff, l1, 2);
    const float inv0 = 1.f / l0;
    const float inv1 = 1.f / l1;

    const int bb = bh >> 5, h = bh & 31;
    const int qr = qt * 128 + rb + g;
    float* o0 = g_ao + ((size_t)(bb * LSEQ + qr)) * DMODEL + (size_t)h * HDIM;
    float* o1 = o0 + (size_t)8 * DMODEL;
#pragma unroll
    for (int nt = 0; nt < 8; nt++) {
        *(float2*)(o0 + nt * 8 + 2 * c) = make_float2(oacc[nt][0] * inv0, oacc[nt][1] * inv0);
        *(float2*)(o1 + nt * 8 + 2 * c) = make_float2(oacc[nt][2] * inv1, oacc[nt][3] * inv1);
    }
}

// ---------------------------------------------------------------------------
extern "C" void kernel_launch(void* const* d_in, const int* in_sizes, int n_in,
                              void* d_out, int out_size) {
    const float* x    = (const float*)d_in[0];
    const float* wqkv = (const float*)d_in[1];
    const float* wo   = (const float*)d_in[2];
    float* out        = (float*)d_out;

    float* qkv = nullptr; cudaGetSymbolAddress((void**)&qkv, g_qkv);
    float* ao  = nullptr; cudaGetSymbolAddress((void**)&ao,  g_ao);

    static bool attr_set = false;
    if (!attr_set) {
        cudaFuncSetAttribute(k_flash_attn_mma,
                             cudaFuncAttributeMaxDynamicSharedMemorySize, FA_SMEM);
        attr_set = true;
    }

    // 1) QKV projection
    {
        dim3 grid(NQKV / 128, MROWS / 128);
        k_gemm_tf32<<<grid, 256>>>(x, wqkv, qkv, NQKV, DMODEL);
    }
    // 2) RoPE + split
    {
        int total = MROWS * NHEAD * 32;
        k_rope_split<<<(total + 255) / 256, 256>>>();
    }
    // 3) Flash attention (double-buffered cp.async pipeline)
    {
        dim3 grid(LSEQ / 128, BSZ * NHEAD);
        k_flash_attn_mma<<<grid, 256, FA_SMEM>>>();
    }
    // 4) Output projection
    {
        dim3 grid(DMODEL / 128, MROWS / 128);
        k_gemm_tf32<<<grid, 256>>>(ao, wo, out, DMODEL, DMODEL);
    }
}

// round 6
// speedup vs baseline: 4.9602x; 1.0475x over previous
#include <cuda_runtime.h>
#include <math.h>
#include <stdint.h>

// Problem constants
#define BSZ 2
#define LSEQ 2048
#define DMODEL 2048
#define NHEAD 32
#define HDIM 64
#define MROWS (BSZ * LSEQ)     // 4096
#define NQKV (3 * DMODEL)      // 6144

// Scratch (device globals)
__device__ float g_qkv[(size_t)MROWS * NQKV];
__device__ float g_q[(size_t)MROWS * DMODEL];   // [B,H,L,hd]
__device__ float g_k[(size_t)MROWS * DMODEL];   // [B,H,L,hd]
__device__ float g_v[(size_t)MROWS * DMODEL];   // [B,H,L,hd]
__device__ float g_ao[(size_t)MROWS * DMODEL];  // [B*L, H*hd]

__device__ __forceinline__ uint32_t f2tf32(float x) {
    uint32_t y;
    asm("cvt.rna.tf32.f32 %0, %1;" : "=r"(y) : "f"(x));
    return y;
}
__device__ __forceinline__ float ex2f(float x) {
    float y;
    asm("ex2.approx.f32 %0, %1;" : "=f"(y) : "f"(x));
    return y;
}
__device__ __forceinline__ void mma_tf32(float* d, const uint32_t* a,
                                         const uint32_t* b) {
    asm volatile(
        "mma.sync.aligned.m16n8k8.row.col.f32.tf32.tf32.f32 "
        "{%0,%1,%2,%3}, {%4,%5,%6,%7}, {%8,%9}, {%0,%1,%2,%3};"
        : "+f"(d[0]), "+f"(d[1]), "+f"(d[2]), "+f"(d[3])
        : "r"(a[0]), "r"(a[1]), "r"(a[2]), "r"(a[3]), "r"(b[0]), "r"(b[1]));
}
__device__ __forceinline__ uint32_t sm_u32(const void* p) {
    uint32_t a;
    asm("{ .reg .u64 t; cvta.to.shared.u64 t, %1; cvt.u32.u64 %0, t; }"
        : "=r"(a) : "l"(p));
    return a;
}
__device__ __forceinline__ void cp16(uint32_t dst, const void* src) {
    asm volatile("cp.async.cg.shared.global [%0], [%1], 16;" :: "r"(dst), "l"(src));
}
#define CP_COMMIT() asm volatile("cp.async.commit_group;")
#define CP_WAIT0()  asm volatile("cp.async.wait_group 0;")

// ---------------------------------------------------------------------------
// TF32 GEMM v2 (NT): C[M,N] = A[M,K] @ B[N,K]^T
// 128x128 block, 4 warps (2x2), 64x64 warp tile, BK=16, cp.async double
// buffer of RAW f32; cvt.rna in registers. K-permuted mma slots: slots
// (c, c+4) take actual k-indices (2c, 2c+1) for both A and B, so every
// fragment pair is a single LDS.64 from naturally-ordered smem.
// M,N multiples of 128; K multiple of 16.
// ---------------------------------------------------------------------------
__global__ void __launch_bounds__(128)
k_gemm_tf32(const float* __restrict__ A, const float* __restrict__ B,
            float* __restrict__ C, int N, int K) {
    __shared__ float As[2][128][16];
    __shared__ float Bs[2][128][16];

    const int tid  = threadIdx.x;
    const int warp = tid >> 5, lane = tid & 31;
    const int row0 = blockIdx.y * 128;
    const int col0 = blockIdx.x * 128;
    const int wr = warp & 1;        // 0..1 -> 64-row slab
    const int wc = warp >> 1;       // 0..1 -> 64-col slab
    const int g  = lane >> 2;       // 0..7
    const int c  = lane & 3;        // 0..3

    const uint32_t sA = sm_u32(&As[0][0][0]);
    const uint32_t sB = sm_u32(&Bs[0][0][0]);

    // staging mapping: chunk u in [0,512): r=u>>2, 16B chunk (u&3)
    const int st_r  = tid >> 2;          // +32 per i
    const int st_c4 = (tid & 3) * 4;

    float acc[4][8][4];
#pragma unroll
    for (int mt = 0; mt < 4; mt++)
#pragma unroll
        for (int nt = 0; nt < 8; nt++)
#pragma unroll
            for (int i = 0; i < 4; i++) acc[mt][nt][i] = 0.f;

    const int nst = K / 16;

    // prologue: stage 0
#pragma unroll
    for (int i = 0; i < 4; i++) {
        int r = st_r + i * 32;
        cp16(sA + (r * 16 + st_c4) * 4, A + (size_t)(row0 + r) * K + st_c4);
        cp16(sB + (r * 16 + st_c4) * 4, B + (size_t)(col0 + r) * K + st_c4);
    }
    CP_COMMIT();

    for (int s = 0; s < nst; s++) {
        CP_WAIT0();
        __syncthreads();

        if (s + 1 < nst) {
            const int b1 = (s + 1) & 1;
            const int k1 = (s + 1) * 16;
#pragma unroll
            for (int i = 0; i < 4; i++) {
                int r = st_r + i * 32;
                cp16(sA + (b1 * 2048 + r * 16 + st_c4) * 4,
                     A + (size_t)(row0 + r) * K + k1 + st_c4);
                cp16(sB + (b1 * 2048 + r * 16 + st_c4) * 4,
                     B + (size_t)(col0 + r) * K + k1 + st_c4);
            }
            CP_COMMIT();
        }

        const int b = s & 1;
#pragma unroll
        for (int ks = 0; ks < 2; ks++) {
            // A fragments: 4 m-tiles, each 2x LDS.64 + 4 cvt
            uint32_t af[4][4];
#pragma unroll
            for (int mt = 0; mt < 4; mt++) {
                int rr = wr * 64 + mt * 16;
                float2 x0 = *(const float2*)&As[b][rr + g][ks * 8 + 2 * c];
                float2 x1 = *(const float2*)&As[b][rr + g + 8][ks * 8 + 2 * c];
                af[mt][0] = f2tf32(x0.x);
                af[mt][2] = f2tf32(x0.y);
                af[mt][1] = f2tf32(x1.x);
                af[mt][3] = f2tf32(x1.y);
            }
#pragma unroll
            for (int nt = 0; nt < 8; nt++) {
                int cc = wc * 64 + nt * 8;
                float2 y = *(const float2*)&Bs[b][cc + g][ks * 8 + 2 * c];
                uint32_t bf[2] = {f2tf32(y.x), f2tf32(y.y)};
#pragma unroll
                for (int mt = 0; mt < 4; mt++)
                    mma_tf32(acc[mt][nt], af[mt], bf);
            }
        }
        __syncthreads();
    }

    // Epilogue
#pragma unroll
    for (int mt = 0; mt < 4; mt++) {
        int r0 = row0 + wr * 64 + mt * 16 + g;
#pragma unroll
        for (int nt = 0; nt < 8; nt++) {
            int cc = col0 + wc * 64 + nt * 8 + c * 2;
            *(float2*)&C[(size_t)r0 * N + cc] = make_float2(acc[mt][nt][0], acc[mt][nt][1]);
            *(float2*)&C[(size_t)(r0 + 8) * N + cc] = make_float2(acc[mt][nt][2], acc[mt][nt][3]);
        }
    }
}

// ---------------------------------------------------------------------------
// RoPE + split (unchanged)
// ---------------------------------------------------------------------------
__global__ void __launch_bounds__(256)
k_rope_split() {
    int idx = blockIdx.x * blockDim.x + threadIdx.x;
    const int d  = idx & 31;
    const int h  = (idx >> 5) & 31;
    const int ml = idx >> 10;
    if (ml >= MROWS) return;
    const int l  = ml & (LSEQ - 1);
    const int b  = ml >> 11;

    const size_t base = (size_t)ml * NQKV + (size_t)h * HDIM;
    float q1 = g_qkv[base + d];
    float q2 = g_qkv[base + d + 32];
    float k1 = g_qkv[base + DMODEL + d];
    float k2 = g_qkv[base + DMODEL + d + 32];
    float v1 = g_qkv[base + 2 * DMODEL + d];
    float v2 = g_qkv[base + 2 * DMODEL + d + 32];

    float inv_freq = exp2f(-9.0f * (float)d / 32.0f);
    float f = (float)l * inv_freq;
    float s, cc;
    sincosf(f, &s, &cc);

    const size_t obase = (((size_t)b * NHEAD + h) * LSEQ + l) * HDIM;
    g_q[obase + d]      = q1 * cc - q2 * s;
    g_q[obase + d + 32] = q2 * cc + q1 * s;
    g_k[obase + d]      = k1 * cc - k2 * s;
    g_k[obase + d + 32] = k2 * cc + k1 * s;
    g_v[obase + d]      = v1;
    g_v[obase + d + 32] = v2;
}

// ---------------------------------------------------------------------------
// Tensor-core flash attention v3 (unchanged from R5): cp.async double-buffered
// K/V pipeline, k-permuted fragments, P in registers.
// ---------------------------------------------------------------------------
#define KSTR 72
#define VRSTR 68
#define FA_WORDS (4 * 64 * KSTR + 2 * 64 * VRSTR)
#define FA_SMEM (FA_WORDS * 4)

__global__ void __launch_bounds__(256)
k_flash_attn_mma() {
    extern __shared__ uint32_t sm[];

    const int tid  = threadIdx.x;
    const int warp = tid >> 5, lane = tid & 31;
    const int g = lane >> 2, c = lane & 3;
    const int qt = gridDim.x - 1 - blockIdx.x;
    const int bh = blockIdx.y;
    const int rb = warp * 16;
    const float qscale = 0.125f * 1.4426950408889634f;

    const uint32_t smb = sm_u32(sm);

    float (*Qs)[KSTR] = (float(*)[KSTR])sm;
    const float* Qg = g_q + ((size_t)bh * LSEQ + (size_t)qt * 128) * HDIM;
#pragma unroll
    for (int i = 0; i < 8; i++) {
        int u = tid + i * 256;
        int r = u >> 4, c4 = (u & 15) * 4;
        *(float4*)&Qs[r][c4] = *(const float4*)(Qg + (size_t)r * HDIM + c4);
    }
    __syncthreads();

    uint32_t af[8][4];
#pragma unroll
    for (int kc = 0; kc < 8; kc++) {
        float2 a0 = *(const float2*)&Qs[rb + g][kc * 8 + 2 * c];
        float2 a1 = *(const float2*)&Qs[rb + g + 8][kc * 8 + 2 * c];
        af[kc][0] = f2tf32(qscale * a0.x);
        af[kc][2] = f2tf32(qscale * a0.y);
        af[kc][1] = f2tf32(qscale * a1.x);
        af[kc][3] = f2tf32(qscale * a1.y);
    }
    __syncthreads();

    const int cp_r  = tid >> 4;
    const int cp_c4 = (tid & 15) * 4;
    const int tv_col = tid & 63;
    const int tv_r0  = (tid >> 6) * 4;

    const float* Kg0 = g_k + (size_t)bh * LSEQ * HDIM;
    const float* Vg0 = g_v + (size_t)bh * LSEQ * HDIM;

    {
        uint32_t ks = smb;
        uint32_t vr = smb + (256 * KSTR) * 4;
#pragma unroll
        for (int i = 0; i < 4; i++) {
            int r = cp_r + i * 16;
            cp16(ks + (r * KSTR + cp_c4) * 4, Kg0 + (size_t)r * HDIM + cp_c4);
            cp16(vr + (r * VRSTR + cp_c4) * 4, Vg0 + (size_t)r * HDIM + cp_c4);
        }
        CP_COMMIT();
        CP_WAIT0();
        __syncthreads();
        uint32_t (*Kb)[KSTR]  = (uint32_t(*)[KSTR])sm;
        float    (*Vr)[VRSTR] = (float(*)[VRSTR])(sm + 256 * KSTR);
        uint32_t (*Vtb)[KSTR] = (uint32_t(*)[KSTR])(sm + 128 * KSTR);
#pragma unroll
        for (int i = 0; i < 4; i++) {
            int r = cp_r + i * 16;
            float4 v = *(float4*)&Kb[r][cp_c4];
            *(uint4*)&Kb[r][cp_c4] = make_uint4(f2tf32(v.x), f2tf32(v.y), f2tf32(v.z), f2tf32(v.w));
        }
#pragma unroll
        for (int i = 0; i < 4; i++) {
            int r = tv_r0 + i * 16;
            uint4 w = make_uint4(f2tf32(Vr[r + 0][tv_col]), f2tf32(Vr[r + 1][tv_col]),
                                 f2tf32(Vr[r + 2][tv_col]), f2tf32(Vr[r + 3][tv_col]));
            *(uint4*)&Vtb[tv_col][r] = w;
        }
        __syncthreads();
    }

    float oacc[8][4];
#pragma unroll
    for (int nt = 0; nt < 8; nt++)
#pragma unroll
        for (int i = 0; i < 4; i++) oacc[nt][i] = 0.f;
    float m0 = -1e30f, m1 = -1e30f, l0 = 0.f, l1 = 0.f;

    const int ktmax = 2 * qt + 1;
    for (int kt = 0; kt <= ktmax; ++kt) {
        const int b = kt & 1;

        if (kt < ktmax) {
            const float* Kg = Kg0 + (size_t)(kt + 1) * 64 * HDIM;
            const float* Vg = Vg0 + (size_t)(kt + 1) * 64 * HDIM;
            uint32_t ks = smb + ((b ^ 1) * 64 * KSTR) * 4;
            uint32_t vr = smb + (256 * KSTR + (b ^ 1) * 64 * VRSTR) * 4;
#pragma unroll
            for (int i = 0; i < 4; i++) {
                int r = cp_r + i * 16;
                cp16(ks + (r * KSTR + cp_c4) * 4, Kg + (size_t)r * HDIM + cp_c4);
                cp16(vr + (r * VRSTR + cp_c4) * 4, Vg + (size_t)r * HDIM + cp_c4);
            }
            CP_COMMIT();
        }

        uint32_t (*Ks)[KSTR] = (uint32_t(*)[KSTR])(sm + b * 64 * KSTR);
        uint32_t (*Vt)[KSTR] = (uint32_t(*)[KSTR])(sm + (128 + b * 64) * KSTR);

        float s[8][4];
#pragma unroll
        for (int nt = 0; nt < 8; nt++) {
            s[nt][0] = s[nt][1] = s[nt][2] = s[nt][3] = 0.f;
#pragma unroll
            for (int kc = 0; kc < 8; kc++) {
                uint2 bb = *(const uint2*)&Ks[nt * 8 + g][kc * 8 + 2 * c];
                uint32_t bf[2] = {bb.x, bb.y};
                mma_tf32(s[nt], af[kc], bf);
            }
        }

        if (kt >= 2 * qt) {
            int qr0 = qt * 128 + rb + g;
            int qr1 = qr0 + 8;
#pragma unroll
            for (int nt = 0; nt < 8; nt++) {
                int col = kt * 64 + nt * 8 + 2 * c;
                if (col > qr0)     s[nt][0] = -1e30f;
                if (col + 1 > qr0) s[nt][1] = -1e30f;
                if (col > qr1)     s[nt][2] = -1e30f;
                if (col + 1 > qr1) s[nt][3] = -1e30f;
            }
        }

        float tm0 = -1e30f, tm1 = -1e30f;
#pragma unroll
        for (int nt = 0; nt < 8; nt++) {
            tm0 = fmaxf(tm0, fmaxf(s[nt][0], s[nt][1]));
            tm1 = fmaxf(tm1, fmaxf(s[nt][2], s[nt][3]));
        }
        tm0 = fmaxf(tm0, __shfl_xor_sync(0xffffffff, tm0, 1));
        tm0 = fmaxf(tm0, __shfl_xor_sync(0xffffffff, tm0, 2));
        tm1 = fmaxf(tm1, __shfl_xor_sync(0xffffffff, tm1, 1));
        tm1 = fmaxf(tm1, __shfl_xor_sync(0xffffffff, tm1, 2));
        float nm0 = fmaxf(m0, tm0);
        float nm1 = fmaxf(m1, tm1);
        float cr0 = ex2f(m0 - nm0);
        float cr1 = ex2f(m1 - nm1);
        m0 = nm0; m1 = nm1;
        l0 *= cr0; l1 *= cr1;
#pragma unroll
        for (int nt = 0; nt < 8; nt++) {
            oacc[nt][0] *= cr0; oacc[nt][1] *= cr0;
            oacc[nt][2] *= cr1; oacc[nt][3] *= cr1;
        }
#pragma unroll
        for (int nt = 0; nt < 8; nt++) {
            s[nt][0] = ex2f(s[nt][0] - nm0);
            s[nt][1] = ex2f(s[nt][1] - nm0);
            s[nt][2] = ex2f(s[nt][2] - nm1);
            s[nt][3] = ex2f(s[nt][3] - nm1);
            l0 += s[nt][0] + s[nt][1];
            l1 += s[nt][2] + s[nt][3];
        }

#pragma unroll
        for (int kc = 0; kc < 8; kc++) {
            uint32_t pa[4];
            pa[0] = f2tf32(s[kc][0]);
            pa[1] = f2tf32(s[kc][2]);
            pa[2] = f2tf32(s[kc][1]);
            pa[3] = f2tf32(s[kc][3]);
#pragma unroll
            for (int nt = 0; nt < 8; nt++) {
                uint2 bb = *(const uint2*)&Vt[nt * 8 + g][kc * 8 + 2 * c];
                uint32_t bf[2] = {bb.x, bb.y};
                mma_tf32(oacc[nt], pa, bf);
            }
        }

        if (kt < ktmax) {
            CP_WAIT0();
            __syncthreads();
            uint32_t (*Kb)[KSTR]  = (uint32_t(*)[KSTR])(sm + (b ^ 1) * 64 * KSTR);
            float    (*Vr)[VRSTR] = (float(*)[VRSTR])(sm + 256 * KSTR + (b ^ 1) * 64 * VRSTR);
            uint32_t (*Vtb)[KSTR] = (uint32_t(*)[KSTR])(sm + (128 + (b ^ 1) * 64) * KSTR);
#pragma unroll
            for (int i = 0; i < 4; i++) {
                int r = cp_r + i * 16;
                float4 v = *(float4*)&Kb[r][cp_c4];
                *(uint4*)&Kb[r][cp_c4] = make_uint4(f2tf32(v.x), f2tf32(v.y), f2tf32(v.z), f2tf32(v.w));
            }
#pragma unroll
            for (int i = 0; i < 4; i++) {
                int r = tv_r0 + i * 16;
                uint4 w = make_uint4(f2tf32(Vr[r + 0][tv_col]), f2tf32(Vr[r + 1][tv_col]),
                                     f2tf32(Vr[r + 2][tv_col]), f2tf32(Vr[r + 3][tv_col]));
                *(uint4*)&Vtb[tv_col][r] = w;
            }
            __syncthreads();
        }
    }

    l0 += __shfl_xor_sync(0xffffffff, l0, 1);
    l0 += __shfl_xor_sync(0xffffffff, l0, 2);
    l1 += __shfl_xor_sync(0xffffffff, l1, 1);
    l1 += __shfl_xor_sync(0xffffffff, l1, 2);
    const float inv0 = 1.f / l0;
    const float inv1 = 1.f / l1;

    const int bb = bh >> 5, h = bh & 31;
    const int qr = qt * 128 + rb + g;
    float* o0 = g_ao + ((size_t)(bb * LSEQ + qr)) * DMODEL + (size_t)h * HDIM;
    float* o1 = o0 + (size_t)8 * DMODEL;
#pragma unroll
    for (int nt = 0; nt < 8; nt++) {
        *(float2*)(o0 + nt * 8 + 2 * c) = make_float2(oacc[nt][0] * inv0, oacc[nt][1] * inv0);
        *(float2*)(o1 + nt * 8 + 2 * c) = make_float2(oacc[nt][2] * inv1, oacc[nt][3] * inv1);
    }
}

// ---------------------------------------------------------------------------
extern "C" void kernel_launch(void* const* d_in, const int* in_sizes, int n_in,
                              void* d_out, int out_size) {
    const float* x    = (const float*)d_in[0];
    const float* wqkv = (const float*)d_in[1];
    const float* wo   = (const float*)d_in[2];
    float* out        = (float*)d_out;

    float* qkv = nullptr; cudaGetSymbolAddress((void**)&qkv, g_qkv);
    float* ao  = nullptr; cudaGetSymbolAddress((void**)&ao,  g_ao);

    static bool attr_set = false;
    if (!attr_set) {
        cudaFuncSetAttribute(k_flash_attn_mma,
                             cudaFuncAttributeMaxDynamicSharedMemorySize, FA_SMEM);
        attr_set = true;
    }

    // 1) QKV projection
    {
        dim3 grid(NQKV / 128, MROWS / 128);
        k_gemm_tf32<<<grid, 128>>>(x, wqkv, qkv, NQKV, DMODEL);
    }
    // 2) RoPE + split
    {
        int total = MROWS * NHEAD * 32;
        k_rope_split<<<(total + 255) / 256, 256>>>();
    }
    // 3) Flash attention
    {
        dim3 grid(LSEQ / 128, BSZ * NHEAD);
        k_flash_attn_mma<<<grid, 256, FA_SMEM>>>();
    }
    // 4) Output projection
    {
        dim3 grid(DMODEL / 128, MROWS / 128);
        k_gemm_tf32<<<grid, 128>>>(ao, wo, out, DMODEL, DMODEL);
    }
}

// round 7
// speedup vs baseline: 5.5646x; 1.1219x over previous
#include <cuda_runtime.h>
#include <math.h>
#include <stdint.h>

// Problem constants
#define BSZ 2
#define LSEQ 2048
#define DMODEL 2048
#define NHEAD 32
#define HDIM 64
#define MROWS (BSZ * LSEQ)     // 4096
#define NQKV (3 * DMODEL)      // 6144

// Scratch (device globals)
__device__ float g_qkv[(size_t)MROWS * NQKV];     // raw f32 QKV
__device__ float g_x [(size_t)MROWS * DMODEL];    // tf32 bits of x
__device__ float g_wq[(size_t)NQKV * DMODEL];     // tf32 bits of wqkv
__device__ float g_wo[(size_t)DMODEL * DMODEL];   // tf32 bits of wo
__device__ float g_q[(size_t)MROWS * DMODEL];     // tf32 bits, q*scale, [B,H,L,hd]
__device__ float g_k[(size_t)MROWS * DMODEL];     // tf32 bits, [B,H,L,hd]
__device__ float g_v[(size_t)MROWS * DMODEL];     // tf32 bits, [B,H,tile,hd,64] (transposed tiles)
__device__ float g_ao[(size_t)MROWS * DMODEL];    // tf32 bits, [B*L, H*hd]

__device__ __forceinline__ uint32_t f2tf32(float x) {
    uint32_t y;
    asm("cvt.rna.tf32.f32 %0, %1;" : "=r"(y) : "f"(x));
    return y;
}
__device__ __forceinline__ float ex2f(float x) {
    float y;
    asm("ex2.approx.f32 %0, %1;" : "=f"(y) : "f"(x));
    return y;
}
__device__ __forceinline__ void mma_tf32(float* d, const uint32_t* a,
                                         const uint32_t* b) {
    asm volatile(
        "mma.sync.aligned.m16n8k8.row.col.f32.tf32.tf32.f32 "
        "{%0,%1,%2,%3}, {%4,%5,%6,%7}, {%8,%9}, {%0,%1,%2,%3};"
        : "+f"(d[0]), "+f"(d[1]), "+f"(d[2]), "+f"(d[3])
        : "r"(a[0]), "r"(a[1]), "r"(a[2]), "r"(a[3]), "r"(b[0]), "r"(b[1]));
}
__device__ __forceinline__ uint32_t sm_u32(const void* p) {
    uint32_t a;
    asm("{ .reg .u64 t; cvta.to.shared.u64 t, %1; cvt.u32.u64 %0, t; }"
        : "=r"(a) : "l"(p));
    return a;
}
__device__ __forceinline__ void cp16(uint32_t dst, const void* src) {
    asm volatile("cp.async.cg.shared.global [%0], [%1], 16;" :: "r"(dst), "l"(src));
}
#define CP_COMMIT() asm volatile("cp.async.commit_group;")
#define CP_WAIT0()  asm volatile("cp.async.wait_group 0;")

// ---------------------------------------------------------------------------
// Elementwise tf32-rna pre-convert (stores tf32 bit patterns as float)
// ---------------------------------------------------------------------------
__global__ void __launch_bounds__(256)
k_cvt(const float* __restrict__ in, float* __restrict__ out, int n4) {
    int i = blockIdx.x * blockDim.x + threadIdx.x;
    if (i >= n4) return;
    float4 v = *(const float4*)(in + (size_t)i * 4);
    uint4 u = make_uint4(f2tf32(v.x), f2tf32(v.y), f2tf32(v.z), f2tf32(v.w));
    *(uint4*)(out + (size_t)i * 4) = u;
}

// ---------------------------------------------------------------------------
// TF32 GEMM v3 (NT): C[M,N] = A[M,K] @ B[N,K]^T. Inputs are tf32 bits.
// 128x128 block, 4 warps (2x2), 64x64 warp tile, BK=32, cp.async double
// buffer, no cvt in mainloop, stride-40 smem (conflict-free LDS.64),
// one barrier per stage. K-permuted mma slots.
// ---------------------------------------------------------------------------
#define GSTR 40
#define GEMM_SMEM (4 * 128 * GSTR * 4)   // A[2]+B[2] = 81920 B

__global__ void __launch_bounds__(128)
k_gemm_tf32(const uint32_t* __restrict__ A, const uint32_t* __restrict__ B,
            float* __restrict__ C, int N, int K) {
    extern __shared__ uint32_t gsm[];
    // A buffer b: gsm + b*128*GSTR ; B buffer b: gsm + (2+b)*128*GSTR
    const uint32_t smb = sm_u32(gsm);

    const int tid  = threadIdx.x;
    const int warp = tid >> 5, lane = tid & 31;
    const int row0 = blockIdx.y * 128;
    const int col0 = blockIdx.x * 128;
    const int wr = warp & 1;
    const int wc = warp >> 1;
    const int g  = lane >> 2;
    const int c  = lane & 3;

    // staging: 1024 16B-chunks per matrix per stage, 8 per thread
    const int st_r  = tid >> 3;          // +16 per i? no: u = tid + i*128, r = u>>3
    const int st_c4 = (tid & 7) * 4;

    float acc[4][8][4];
#pragma unroll
    for (int mt = 0; mt < 4; mt++)
#pragma unroll
        for (int nt = 0; nt < 8; nt++)
#pragma unroll
            for (int i = 0; i < 4; i++) acc[mt][nt][i] = 0.f;

    const int nst = K / 32;

    // prologue: stage 0
#pragma unroll
    for (int i = 0; i < 8; i++) {
        int r = st_r + i * 16;
        cp16(smb + (r * GSTR + st_c4) * 4, A + (size_t)(row0 + r) * K + st_c4);
        cp16(smb + ((2 * 128 + r) * GSTR + st_c4) * 4, B + (size_t)(col0 + r) * K + st_c4);
    }
    CP_COMMIT();

    for (int s = 0; s < nst; s++) {
        CP_WAIT0();
        __syncthreads();

        if (s + 1 < nst) {
            const int b1 = (s + 1) & 1;
            const int k1 = (s + 1) * 32;
#pragma unroll
            for (int i = 0; i < 8; i++) {
                int r = st_r + i * 16;
                cp16(smb + ((b1 * 128 + r) * GSTR + st_c4) * 4,
                     A + (size_t)(row0 + r) * K + k1 + st_c4);
                cp16(smb + (((2 + b1) * 128 + r) * GSTR + st_c4) * 4,
                     B + (size_t)(col0 + r) * K + k1 + st_c4);
            }
            CP_COMMIT();
        }

        const int b = s & 1;
        const uint32_t (*As)[GSTR] = (const uint32_t(*)[GSTR])(gsm + b * 128 * GSTR);
        const uint32_t (*Bs)[GSTR] = (const uint32_t(*)[GSTR])(gsm + (2 + b) * 128 * GSTR);

#pragma unroll
        for (int ks = 0; ks < 4; ks++) {
            uint32_t af[4][4];
#pragma unroll
            for (int mt = 0; mt < 4; mt++) {
                int rr = wr * 64 + mt * 16;
                uint2 x0 = *(const uint2*)&As[rr + g][ks * 8 + 2 * c];
                uint2 x1 = *(const uint2*)&As[rr + g + 8][ks * 8 + 2 * c];
                af[mt][0] = x0.x; af[mt][2] = x0.y;
                af[mt][1] = x1.x; af[mt][3] = x1.y;
            }
#pragma unroll
            for (int nt = 0; nt < 8; nt++) {
                int cc = wc * 64 + nt * 8;
                uint2 y = *(const uint2*)&Bs[cc + g][ks * 8 + 2 * c];
                uint32_t bf[2] = {y.x, y.y};
#pragma unroll
                for (int mt = 0; mt < 4; mt++)
                    mma_tf32(acc[mt][nt], af[mt], bf);
            }
        }
    }

    // Epilogue
#pragma unroll
    for (int mt = 0; mt < 4; mt++) {
        int r0 = row0 + wr * 64 + mt * 16 + g;
#pragma unroll
        for (int nt = 0; nt < 8; nt++) {
            int cc = col0 + wc * 64 + nt * 8 + c * 2;
            *(float2*)&C[(size_t)r0 * N + cc] = make_float2(acc[mt][nt][0], acc[mt][nt][1]);
            *(float2*)&C[(size_t)(r0 + 8) * N + cc] = make_float2(acc[mt][nt][2], acc[mt][nt][3]);
        }
    }
}

// ---------------------------------------------------------------------------
// RoPE + split. Writes tf32 BIT PATTERNS:
//  g_q = tf32(qscale * rot(q))   [B,H,L,hd], qscale = 0.125*log2(e)
//  g_k = tf32(rot(k))            [B,H,L,hd]
//  g_v = tf32(v) TRANSPOSED per 64-token tile: [B,H, t, hd, 64]
// ---------------------------------------------------------------------------
__global__ void __launch_bounds__(256)
k_rope_split() {
    int idx = blockIdx.x * blockDim.x + threadIdx.x;
    const int d  = idx & 31;
    const int h  = (idx >> 5) & 31;
    const int ml = idx >> 10;
    if (ml >= MROWS) return;
    const int l  = ml & (LSEQ - 1);
    const int b  = ml >> 11;
    const float qscale = 0.125f * 1.4426950408889634f;

    const size_t base = (size_t)ml * NQKV + (size_t)h * HDIM;
    float q1 = g_qkv[base + d];
    float q2 = g_qkv[base + d + 32];
    float k1 = g_qkv[base + DMODEL + d];
    float k2 = g_qkv[base + DMODEL + d + 32];
    float v1 = g_qkv[base + 2 * DMODEL + d];
    float v2 = g_qkv[base + 2 * DMODEL + d + 32];

    float inv_freq = exp2f(-9.0f * (float)d / 32.0f);
    float f = (float)l * inv_freq;
    float s, cc;
    sincosf(f, &s, &cc);

    const int bh = b * NHEAD + h;
    const size_t obase = ((size_t)bh * LSEQ + l) * HDIM;
    ((uint32_t*)g_q)[obase + d]      = f2tf32(qscale * (q1 * cc - q2 * s));
    ((uint32_t*)g_q)[obase + d + 32] = f2tf32(qscale * (q2 * cc + q1 * s));
    ((uint32_t*)g_k)[obase + d]      = f2tf32(k1 * cc - k2 * s);
    ((uint32_t*)g_k)[obase + d + 32] = f2tf32(k2 * cc + k1 * s);

    const int t = l >> 6, lc = l & 63;
    const size_t vbase = (((size_t)bh * 32 + t) * HDIM) * 64 + lc;
    ((uint32_t*)g_v)[vbase + (size_t)d * 64]        = f2tf32(v1);
    ((uint32_t*)g_v)[vbase + (size_t)(d + 32) * 64] = f2tf32(v2);
}

// ---------------------------------------------------------------------------
// Flash attention v4: inputs pre-tf32 (no cvt), V pre-transposed (no smem
// transpose pass), 1 barrier per k-tile, cp.async double buffer.
// Grid: (L/128, B*H). Block: 256 threads / 8 warps.
// smem: Ks[2][64][72] + Vt[2][64][72]; Q staging aliases Ks.
// ---------------------------------------------------------------------------
#define FKSTR 72
#define FA_SMEM (4 * 64 * FKSTR * 4)   // 73728 B

__global__ void __launch_bounds__(256)
k_flash_attn_mma() {
    extern __shared__ uint32_t sm[];
    const uint32_t smb = sm_u32(sm);

    const int tid  = threadIdx.x;
    const int warp = tid >> 5, lane = tid & 31;
    const int g = lane >> 2, c = lane & 3;
    const int qt = gridDim.x - 1 - blockIdx.x;
    const int bh = blockIdx.y;
    const int rb = warp * 16;

    // ---- Prologue: stage Q (tf32 bits) into Ks-alias, build A-frags --------
    uint32_t (*Qs)[FKSTR] = (uint32_t(*)[FKSTR])sm;   // 128 x 72, aliases Ks
    const uint32_t* Qg =
        (const uint32_t*)g_q + ((size_t)bh * LSEQ + (size_t)qt * 128) * HDIM;
#pragma unroll
    for (int i = 0; i < 8; i++) {
        int u = tid + i * 256;
        int r = u >> 4, c4 = (u & 15) * 4;
        *(uint4*)&Qs[r][c4] = *(const uint4*)(Qg + (size_t)r * HDIM + c4);
    }
    __syncthreads();

    uint32_t af[8][4];
#pragma unroll
    for (int kc = 0; kc < 8; kc++) {
        uint2 a0 = *(const uint2*)&Qs[rb + g][kc * 8 + 2 * c];
        uint2 a1 = *(const uint2*)&Qs[rb + g + 8][kc * 8 + 2 * c];
        af[kc][0] = a0.x; af[kc][2] = a0.y;
        af[kc][1] = a1.x; af[kc][3] = a1.y;
    }
    __syncthreads();   // Q region dead

    const int cp_r  = tid >> 4;
    const int cp_c4 = (tid & 15) * 4;

    const uint32_t* Kg0 = (const uint32_t*)g_k + (size_t)bh * LSEQ * HDIM;
    const uint32_t* Vg0 = (const uint32_t*)g_v + (size_t)bh * 32 * 4096;

    // issue tile 0 into buffer 0
#pragma unroll
    for (int i = 0; i < 4; i++) {
        int r = cp_r + i * 16;
        cp16(smb + (r * FKSTR + cp_c4) * 4, Kg0 + (size_t)r * HDIM + cp_c4);
        cp16(smb + ((128 + r) * FKSTR + cp_c4) * 4, Vg0 + (size_t)r * 64 + cp_c4);
    }
    CP_COMMIT();

    float oacc[8][4];
#pragma unroll
    for (int nt = 0; nt < 8; nt++)
#pragma unroll
        for (int i = 0; i < 4; i++) oacc[nt][i] = 0.f;
    float m0 = -1e30f, m1 = -1e30f, l0 = 0.f, l1 = 0.f;

    const int ktmax = 2 * qt + 1;
    for (int kt = 0; kt <= ktmax; ++kt) {
        const int b = kt & 1;
        CP_WAIT0();
        __syncthreads();

        if (kt < ktmax) {
            const uint32_t* Kg = Kg0 + (size_t)(kt + 1) * 64 * HDIM;
            const uint32_t* Vg = Vg0 + (size_t)(kt + 1) * 4096;
            const int b1 = b ^ 1;
#pragma unroll
            for (int i = 0; i < 4; i++) {
                int r = cp_r + i * 16;
                cp16(smb + ((b1 * 64 + r) * FKSTR + cp_c4) * 4,
                     Kg + (size_t)r * HDIM + cp_c4);
                cp16(smb + ((128 + b1 * 64 + r) * FKSTR + cp_c4) * 4,
                     Vg + (size_t)r * 64 + cp_c4);
            }
            CP_COMMIT();
        }

        const uint32_t (*Ks)[FKSTR] = (const uint32_t(*)[FKSTR])(sm + b * 64 * FKSTR);
        const uint32_t (*Vt)[FKSTR] = (const uint32_t(*)[FKSTR])(sm + (128 + b * 64) * FKSTR);

        // S = Q @ K^T (log2 domain, scale pre-folded into Q)
        float s[8][4];
#pragma unroll
        for (int nt = 0; nt < 8; nt++) {
            s[nt][0] = s[nt][1] = s[nt][2] = s[nt][3] = 0.f;
#pragma unroll
            for (int kc = 0; kc < 8; kc++) {
                uint2 bb = *(const uint2*)&Ks[nt * 8 + g][kc * 8 + 2 * c];
                uint32_t bf[2] = {bb.x, bb.y};
                mma_tf32(s[nt], af[kc], bf);
            }
        }

        if (kt >= 2 * qt) {
            int qr0 = qt * 128 + rb + g;
            int qr1 = qr0 + 8;
#pragma unroll
            for (int nt = 0; nt < 8; nt++) {
                int col = kt * 64 + nt * 8 + 2 * c;
                if (col > qr0)     s[nt][0] = -1e30f;
                if (col + 1 > qr0) s[nt][1] = -1e30f;
                if (col > qr1)     s[nt][2] = -1e30f;
                if (col + 1 > qr1) s[nt][3] = -1e30f;
            }
        }

        float tm0 = -1e30f, tm1 = -1e30f;
#pragma unroll
        for (int nt = 0; nt < 8; nt++) {
            tm0 = fmaxf(tm0, fmaxf(s[nt][0], s[nt][1]));
            tm1 = fmaxf(tm1, fmaxf(s[nt][2], s[nt][3]));
        }
        tm0 = fmaxf(tm0, __shfl_xor_sync(0xffffffff, tm0, 1));
        tm0 = fmaxf(tm0, __shfl_xor_sync(0xffffffff, tm0, 2));
        tm1 = fmaxf(tm1, __shfl_xor_sync(0xffffffff, tm1, 1));
        tm1 = fmaxf(tm1, __shfl_xor_sync(0xffffffff, tm1, 2));
        float nm0 = fmaxf(m0, tm0);
        float nm1 = fmaxf(m1, tm1);
        float cr0 = ex2f(m0 - nm0);
        float cr1 = ex2f(m1 - nm1);
        m0 = nm0; m1 = nm1;
        l0 *= cr0; l1 *= cr1;
#pragma unroll
        for (int nt = 0; nt < 8; nt++) {
            oacc[nt][0] *= cr0; oacc[nt][1] *= cr0;
            oacc[nt][2] *= cr1; oacc[nt][3] *= cr1;
        }
#pragma unroll
        for (int nt = 0; nt < 8; nt++) {
            s[nt][0] = ex2f(s[nt][0] - nm0);
            s[nt][1] = ex2f(s[nt][1] - nm0);
            s[nt][2] = ex2f(s[nt][2] - nm1);
            s[nt][3] = ex2f(s[nt][3] - nm1);
            l0 += s[nt][0] + s[nt][1];
            l1 += s[nt][2] + s[nt][3];
        }

        // O += P @ V (P in registers, k-permuted)
#pragma unroll
        for (int kc = 0; kc < 8; kc++) {
            uint32_t pa[4];
            pa[0] = f2tf32(s[kc][0]);
            pa[1] = f2tf32(s[kc][2]);
            pa[2] = f2tf32(s[kc][1]);
            pa[3] = f2tf32(s[kc][3]);
#pragma unroll
            for (int nt = 0; nt < 8; nt++) {
                uint2 bb = *(const uint2*)&Vt[nt * 8 + g][kc * 8 + 2 * c];
                uint32_t bf[2] = {bb.x, bb.y};
                mma_tf32(oacc[nt], pa, bf);
            }
        }
    }

    l0 += __shfl_xor_sync(0xffffffff, l0, 1);
    l0 += __shfl_xor_sync(0xffffffff, l0, 2);
    l1 += __shfl_xor_sync(0xffffffff, l1, 1);
    l1 += __shfl_xor_sync(0xffffffff, l1, 2);
    const float inv0 = 1.f / l0;
    const float inv1 = 1.f / l1;

    const int bb = bh >> 5, h = bh & 31;
    const int qr = qt * 128 + rb + g;
    uint32_t* o0 = (uint32_t*)g_ao + ((size_t)(bb * LSEQ + qr)) * DMODEL + (size_t)h * HDIM;
    uint32_t* o1 = o0 + (size_t)8 * DMODEL;
#pragma unroll
    for (int nt = 0; nt < 8; nt++) {
        uint2 r0 = make_uint2(f2tf32(oacc[nt][0] * inv0), f2tf32(oacc[nt][1] * inv0));
        uint2 r1 = make_uint2(f2tf32(oacc[nt][2] * inv1), f2tf32(oacc[nt][3] * inv1));
        *(uint2*)(o0 + nt * 8 + 2 * c) = r0;
        *(uint2*)(o1 + nt * 8 + 2 * c) = r1;
    }
}

// ---------------------------------------------------------------------------
extern "C" void kernel_launch(void* const* d_in, const int* in_sizes, int n_in,
                              void* d_out, int out_size) {
    const float* x    = (const float*)d_in[0];
    const float* wqkv = (const float*)d_in[1];
    const float* wo   = (const float*)d_in[2];
    float* out        = (float*)d_out;

    float *qkv, *xc, *wqc, *woc, *ao;
    cudaGetSymbolAddress((void**)&qkv, g_qkv);
    cudaGetSymbolAddress((void**)&xc,  g_x);
    cudaGetSymbolAddress((void**)&wqc, g_wq);
    cudaGetSymbolAddress((void**)&woc, g_wo);
    cudaGetSymbolAddress((void**)&ao,  g_ao);

    static bool attr_set = false;
    if (!attr_set) {
        cudaFuncSetAttribute(k_flash_attn_mma,
                             cudaFuncAttributeMaxDynamicSharedMemorySize, FA_SMEM);
        cudaFuncSetAttribute(k_gemm_tf32,
                             cudaFuncAttributeMaxDynamicSharedMemorySize, GEMM_SMEM);
        attr_set = true;
    }

    // 0) pre-convert inputs to tf32 bits
    {
        int n4;
        n4 = MROWS * DMODEL / 4;  k_cvt<<<(n4 + 255) / 256, 256>>>(x, xc, n4);
        n4 = NQKV * DMODEL / 4;   k_cvt<<<(n4 + 255) / 256, 256>>>(wqkv, wqc, n4);
        n4 = DMODEL * DMODEL / 4; k_cvt<<<(n4 + 255) / 256, 256>>>(wo, woc, n4);
    }
    // 1) QKV projection
    {
        dim3 grid(NQKV / 128, MROWS / 128);
        k_gemm_tf32<<<grid, 128, GEMM_SMEM>>>((const uint32_t*)xc,
                                              (const uint32_t*)wqc, qkv,
                                              NQKV, DMODEL);
    }
    // 2) RoPE + split (+ tf32 conversion + V tile transpose)
    {
        int total = MROWS * NHEAD * 32;
        k_rope_split<<<(total + 255) / 256, 256>>>();
    }
    // 3) Flash attention
    {
        dim3 grid(LSEQ / 128, BSZ * NHEAD);
        k_flash_attn_mma<<<grid, 256, FA_SMEM>>>();
    }
    // 4) Output projection
    {
        dim3 grid(DMODEL / 128, MROWS / 128);
        k_gemm_tf32<<<grid, 128, GEMM_SMEM>>>((const uint32_t*)ao,
                                              (const uint32_t*)woc, out,
                                              DMODEL, DMODEL);
    }
}